// round 1
// baseline (speedup 1.0000x reference)
#include <cuda_runtime.h>
#include <cuda_bf16.h>
#include <cstdint>

#define D 128
#define MAXN 50176   // >= max(N_U, N_V)

// Scratch (no cudaMalloc allowed) — two ping-pong feature buffers.
__device__ float g_bufA[(size_t)MAXN * D];
__device__ float g_bufB[(size_t)MAXN * D];

// ---------------------------------------------------------------------------
// Y[i][j] = b[j] + sum_k X[i][k] * W[k][j]
// Block: 256 threads, 32 rows per block.
// Thread (c = tid&31, g = tid>>5): cols 4c..4c+3, rows g*4..g*4+3.
// W staged in smem (64KB), X tile staged in smem (16KB).
// ---------------------------------------------------------------------------
__global__ __launch_bounds__(256, 2)
void gemm_bias_kernel(const float* __restrict__ X,
                      const float* __restrict__ W,
                      const float* __restrict__ b,
                      float* __restrict__ Y,
                      int N)
{
    extern __shared__ float smem[];
    float* sW = smem;            // 128*128
    float* sx = smem + D * D;    // 32*128

    const int tid = threadIdx.x;
    const int rowBase = blockIdx.x * 32;

    // Load W into smem (vectorized)
    {
        const float4* W4 = reinterpret_cast<const float4*>(W);
        float4* sW4 = reinterpret_cast<float4*>(sW);
        #pragma unroll
        for (int i = tid; i < (D * D) / 4; i += 256) sW4[i] = W4[i];
    }
    // Load 32 rows of X into smem (zero-pad OOB rows)
    {
        #pragma unroll
        for (int i = tid; i < 32 * (D / 4); i += 256) {
            int r = i / (D / 4);
            int k4 = i % (D / 4);
            int row = rowBase + r;
            float4 v = make_float4(0.f, 0.f, 0.f, 0.f);
            if (row < N)
                v = reinterpret_cast<const float4*>(X + (size_t)row * D)[k4];
            reinterpret_cast<float4*>(sx)[i] = v;
        }
    }
    __syncthreads();

    const int c = tid & 31;    // column group: cols 4c..4c+3
    const int g = tid >> 5;    // row group:    rows g*4..g*4+3

    const float4 bias = reinterpret_cast<const float4*>(b)[c];

    float acc[4][4];
    #pragma unroll
    for (int r = 0; r < 4; r++) {
        acc[r][0] = bias.x; acc[r][1] = bias.y;
        acc[r][2] = bias.z; acc[r][3] = bias.w;
    }

    const float4* sW4 = reinterpret_cast<const float4*>(sW);
    const float* sx0 = sx + (g * 4 + 0) * D;
    const float* sx1 = sx + (g * 4 + 1) * D;
    const float* sx2 = sx + (g * 4 + 2) * D;
    const float* sx3 = sx + (g * 4 + 3) * D;

    #pragma unroll 8
    for (int k = 0; k < D; k++) {
        float4 w = sW4[k * 32 + c];
        float x0 = sx0[k], x1 = sx1[k], x2 = sx2[k], x3 = sx3[k];
        acc[0][0] += x0 * w.x; acc[0][1] += x0 * w.y; acc[0][2] += x0 * w.z; acc[0][3] += x0 * w.w;
        acc[1][0] += x1 * w.x; acc[1][1] += x1 * w.y; acc[1][2] += x1 * w.z; acc[1][3] += x1 * w.w;
        acc[2][0] += x2 * w.x; acc[2][1] += x2 * w.y; acc[2][2] += x2 * w.z; acc[2][3] += x2 * w.w;
        acc[3][0] += x3 * w.x; acc[3][1] += x3 * w.y; acc[3][2] += x3 * w.z; acc[3][3] += x3 * w.w;
    }

    #pragma unroll
    for (int r = 0; r < 4; r++) {
        int row = rowBase + g * 4 + r;
        if (row < N) {
            float4 o = make_float4(acc[r][0], acc[r][1], acc[r][2], acc[r][3]);
            reinterpret_cast<float4*>(Y + (size_t)row * D)[c] = o;
        }
    }
}

// ---------------------------------------------------------------------------
// dst[idx_dst[e]] += src[idx_src[e]]   (row-wise, D=128)
// One warp per edge; lane handles float4 (32 lanes * 4 = 128 floats).
// Vectorized reduction: red.global.add.v4.f32
// ---------------------------------------------------------------------------
__global__ __launch_bounds__(256)
void scatter_add_kernel(const float* __restrict__ src,
                        float* __restrict__ dst,
                        const int* __restrict__ idx_src,
                        const int* __restrict__ idx_dst,
                        int E)
{
    int warpInBlock = threadIdx.x >> 5;
    int lane = threadIdx.x & 31;
    int e = blockIdx.x * 8 + warpInBlock;
    if (e >= E) return;

    int s = idx_src[e];
    int d = idx_dst[e];

    float4 v = reinterpret_cast<const float4*>(src + (size_t)s * D)[lane];
    float* dp = dst + (size_t)d * D + lane * 4;

    asm volatile("red.global.add.v4.f32 [%0], {%1, %2, %3, %4};"
                 :: "l"(dp), "f"(v.x), "f"(v.y), "f"(v.z), "f"(v.w)
                 : "memory");
}

// ---------------------------------------------------------------------------
// Zero-fill (float4 grid-stride)
// ---------------------------------------------------------------------------
__global__ __launch_bounds__(256)
void zero_kernel(float4* __restrict__ p, int n4)
{
    int i = blockIdx.x * blockDim.x + threadIdx.x;
    int stride = gridDim.x * blockDim.x;
    float4 z = make_float4(0.f, 0.f, 0.f, 0.f);
    for (; i < n4; i += stride) p[i] = z;
}

// ---------------------------------------------------------------------------
// Launch sequence:
//   bufA = X_v @ W0 + b0
//   bufB = 0; bufB[edge_u] += bufA[edge_v]        (v2u)
//   bufA = bufB @ W1 + b1
//   bufB = 0; bufB[edge_v] += bufA[edge_u]        (u2v)
//   bufA = bufB @ W2 + b2
//   out  = 0; out[edge_u]  += bufA[edge_v]        (v2u)
// ---------------------------------------------------------------------------
extern "C" void kernel_launch(void* const* d_in, const int* in_sizes, int n_in,
                              void* d_out, int out_size)
{
    const float* X_v    = (const float*)d_in[1];
    const int*   edge_u = (const int*)  d_in[2];
    const int*   edge_v = (const int*)  d_in[3];
    const float* W0     = (const float*)d_in[4];
    const float* b0     = (const float*)d_in[5];
    const float* W1     = (const float*)d_in[6];
    const float* b1     = (const float*)d_in[7];
    const float* W2     = (const float*)d_in[8];
    const float* b2     = (const float*)d_in[9];
    float*       out    = (float*)d_out;

    const int N_V = in_sizes[1] / D;
    const int E   = in_sizes[2];
    const int N_U = out_size / D;

    float *bufA, *bufB;
    cudaGetSymbolAddress((void**)&bufA, g_bufA);
    cudaGetSymbolAddress((void**)&bufB, g_bufB);

    const int smemBytes = (D * D + 32 * D) * (int)sizeof(float); // 80 KB
    static bool attrSet = false;
    cudaFuncSetAttribute(gemm_bias_kernel,
                         cudaFuncAttributeMaxDynamicSharedMemorySize, smemBytes);
    (void)attrSet;

    const int gemmBlocksV = (N_V + 31) / 32;
    const int gemmBlocksU = (N_U + 31) / 32;
    const int scatBlocks  = (E + 7) / 8;
    const int zeroBlocksU = ((N_U * (D / 4)) + 255) / 256;
    const int zeroBlocksV = ((N_V * (D / 4)) + 255) / 256;

    // Layer 0: Linear on X_v, then v2u
    gemm_bias_kernel<<<gemmBlocksV, 256, smemBytes>>>(X_v, W0, b0, bufA, N_V);
    zero_kernel<<<zeroBlocksU, 256>>>((float4*)bufB, N_U * (D / 4));
    scatter_add_kernel<<<scatBlocks, 256>>>(bufA, bufB, edge_v, edge_u, E);

    // Layer 1: Linear on aggregated U, then u2v
    gemm_bias_kernel<<<gemmBlocksU, 256, smemBytes>>>(bufB, W1, b1, bufA, N_U);
    zero_kernel<<<zeroBlocksV, 256>>>((float4*)bufB, N_V * (D / 4));
    scatter_add_kernel<<<scatBlocks, 256>>>(bufA, bufB, edge_u, edge_v, E);

    // Layer 2: Linear on aggregated V, then v2u into output
    gemm_bias_kernel<<<gemmBlocksV, 256, smemBytes>>>(bufB, W2, b2, bufA, N_V);
    zero_kernel<<<zeroBlocksU, 256>>>((float4*)out, N_U * (D / 4));
    scatter_add_kernel<<<scatBlocks, 256>>>(bufA, out, edge_v, edge_u, E);
}

// round 2
// speedup vs baseline: 1.0614x; 1.0614x over previous
#include <cuda_runtime.h>
#include <cuda_bf16.h>
#include <cstdint>

#define D 128
#define MAXN 50176   // >= max(N_U, N_V)

typedef unsigned long long u64;

// Scratch (no cudaMalloc allowed) — two ping-pong feature buffers.
__device__ float g_bufA[(size_t)MAXN * D];
__device__ float g_bufB[(size_t)MAXN * D];

// ---------------------------------------------------------------------------
// Packed fp32x2 helpers (Blackwell dual-fp32 datapath; exact fp32 semantics)
// ---------------------------------------------------------------------------
__device__ __forceinline__ u64 pack2(float a, float b) {
    u64 r;
    asm("mov.b64 %0, {%1, %2};" : "=l"(r) : "f"(a), "f"(b));
    return r;
}
__device__ __forceinline__ void unpack2(u64 v, float& lo, float& hi) {
    asm("mov.b64 {%0, %1}, %2;" : "=f"(lo), "=f"(hi) : "l"(v));
}
__device__ __forceinline__ void ffma2(u64& d, u64 a, u64 b) {
    asm("fma.rn.f32x2 %0, %1, %2, %0;" : "+l"(d) : "l"(a), "l"(b));
}

// ---------------------------------------------------------------------------
// Y[i][j] = b[j] + sum_k X[i][k] * W[k][j]   via packed f32x2 FMA.
// Block: 256 threads = 8 warps, 64 rows/block (8 rows per warp).
// Lane c handles cols 4c..4c+3. Row pairs packed in f32x2 (X tile transposed
// in smem so a row pair is one LDS.64; W value duplicated into both halves).
// smem: W[128][128] (64KB) + XT[128][64] (32KB) = 96KB.
// ---------------------------------------------------------------------------
__global__ __launch_bounds__(256, 2)
void gemm_bias_kernel(const float* __restrict__ X,
                      const float* __restrict__ W,
                      const float* __restrict__ b,
                      float* __restrict__ Y,
                      int N)
{
    extern __shared__ float smem[];
    float* sW  = smem;            // [128][128]
    float* sXT = smem + D * D;    // [k][row] : [128][64]

    const int tid = threadIdx.x;
    const int rowBase = blockIdx.x * 64;

    // Load W into smem (vectorized, coalesced)
    {
        const float4* W4 = reinterpret_cast<const float4*>(W);
        float4* sW4 = reinterpret_cast<float4*>(sW);
        #pragma unroll
        for (int i = tid; i < (D * D) / 4; i += 256) sW4[i] = W4[i];
    }
    // Load 64 rows of X, transposed into sXT[k][row] (zero-pad OOB rows).
    // Mapping: lane index -> row so STS is conflict-free.
    {
        #pragma unroll
        for (int i = tid; i < 64 * (D / 4); i += 256) {
            int r  = i & 63;    // row within tile
            int k4 = i >> 6;    // float4 index along k
            float4 v = make_float4(0.f, 0.f, 0.f, 0.f);
            int row = rowBase + r;
            if (row < N)
                v = reinterpret_cast<const float4*>(X + (size_t)row * D)[k4];
            sXT[(k4 * 4 + 0) * 64 + r] = v.x;
            sXT[(k4 * 4 + 1) * 64 + r] = v.y;
            sXT[(k4 * 4 + 2) * 64 + r] = v.z;
            sXT[(k4 * 4 + 3) * 64 + r] = v.w;
        }
    }
    __syncthreads();

    const int lane = tid & 31;
    const int warp = tid >> 5;
    const int wr   = warp * 8;          // this warp's first row (within tile)

    // acc[rp][j]: rows (wr+2rp, wr+2rp+1), col lane*4+j, packed (lo=row0, hi=row1)
    u64 acc[4][4];
    {
        const float4 bv = reinterpret_cast<const float4*>(b)[lane];
        #pragma unroll
        for (int rp = 0; rp < 4; rp++) {
            acc[rp][0] = pack2(bv.x, bv.x);
            acc[rp][1] = pack2(bv.y, bv.y);
            acc[rp][2] = pack2(bv.z, bv.z);
            acc[rp][3] = pack2(bv.w, bv.w);
        }
    }

    const float4* sWc = reinterpret_cast<const float4*>(sW) + lane;
    const float*  sx  = sXT + wr;

    #pragma unroll 8
    for (int k = 0; k < D; k++) {
        float4 w = sWc[k * 32];
        u64 wd0 = pack2(w.x, w.x);
        u64 wd1 = pack2(w.y, w.y);
        u64 wd2 = pack2(w.z, w.z);
        u64 wd3 = pack2(w.w, w.w);

        const float* xk = sx + k * 64;
        u64 x0 = *reinterpret_cast<const u64*>(xk + 0);
        u64 x1 = *reinterpret_cast<const u64*>(xk + 2);
        u64 x2 = *reinterpret_cast<const u64*>(xk + 4);
        u64 x3 = *reinterpret_cast<const u64*>(xk + 6);

        ffma2(acc[0][0], x0, wd0); ffma2(acc[0][1], x0, wd1);
        ffma2(acc[0][2], x0, wd2); ffma2(acc[0][3], x0, wd3);
        ffma2(acc[1][0], x1, wd0); ffma2(acc[1][1], x1, wd1);
        ffma2(acc[1][2], x1, wd2); ffma2(acc[1][3], x1, wd3);
        ffma2(acc[2][0], x2, wd0); ffma2(acc[2][1], x2, wd1);
        ffma2(acc[2][2], x2, wd2); ffma2(acc[2][3], x2, wd3);
        ffma2(acc[3][0], x3, wd0); ffma2(acc[3][1], x3, wd1);
        ffma2(acc[3][2], x3, wd2); ffma2(acc[3][3], x3, wd3);
    }

    #pragma unroll
    for (int rp = 0; rp < 4; rp++) {
        int row0 = rowBase + wr + rp * 2;
        float lo0, hi0, lo1, hi1, lo2, hi2, lo3, hi3;
        unpack2(acc[rp][0], lo0, hi0);
        unpack2(acc[rp][1], lo1, hi1);
        unpack2(acc[rp][2], lo2, hi2);
        unpack2(acc[rp][3], lo3, hi3);
        if (row0 < N)
            reinterpret_cast<float4*>(Y + (size_t)row0 * D)[lane] =
                make_float4(lo0, lo1, lo2, lo3);
        if (row0 + 1 < N)
            reinterpret_cast<float4*>(Y + (size_t)(row0 + 1) * D)[lane] =
                make_float4(hi0, hi1, hi2, hi3);
    }
}

// ---------------------------------------------------------------------------
// dst[idx_dst[e]] += src[idx_src[e]]   (row-wise, D=128)
// One warp per edge; lane handles float4. red.global.add.v4.f32.
// ---------------------------------------------------------------------------
__global__ __launch_bounds__(256)
void scatter_add_kernel(const float* __restrict__ src,
                        float* __restrict__ dst,
                        const int* __restrict__ idx_src,
                        const int* __restrict__ idx_dst,
                        int E)
{
    int warpInBlock = threadIdx.x >> 5;
    int lane = threadIdx.x & 31;
    int e = blockIdx.x * 8 + warpInBlock;
    if (e >= E) return;

    int s = idx_src[e];
    int d = idx_dst[e];

    float4 v = reinterpret_cast<const float4*>(src + (size_t)s * D)[lane];
    float* dp = dst + (size_t)d * D + lane * 4;

    asm volatile("red.global.add.v4.f32 [%0], {%1, %2, %3, %4};"
                 :: "l"(dp), "f"(v.x), "f"(v.y), "f"(v.z), "f"(v.w)
                 : "memory");
}

// ---------------------------------------------------------------------------
// Zero-fill (float4 grid-stride)
// ---------------------------------------------------------------------------
__global__ __launch_bounds__(256)
void zero_kernel(float4* __restrict__ p, int n4)
{
    int i = blockIdx.x * blockDim.x + threadIdx.x;
    int stride = gridDim.x * blockDim.x;
    float4 z = make_float4(0.f, 0.f, 0.f, 0.f);
    for (; i < n4; i += stride) p[i] = z;
}

// ---------------------------------------------------------------------------
extern "C" void kernel_launch(void* const* d_in, const int* in_sizes, int n_in,
                              void* d_out, int out_size)
{
    const float* X_v    = (const float*)d_in[1];
    const int*   edge_u = (const int*)  d_in[2];
    const int*   edge_v = (const int*)  d_in[3];
    const float* W0     = (const float*)d_in[4];
    const float* b0     = (const float*)d_in[5];
    const float* W1     = (const float*)d_in[6];
    const float* b1     = (const float*)d_in[7];
    const float* W2     = (const float*)d_in[8];
    const float* b2     = (const float*)d_in[9];
    float*       out    = (float*)d_out;

    const int N_V = in_sizes[1] / D;
    const int E   = in_sizes[2];
    const int N_U = out_size / D;

    float *bufA, *bufB;
    cudaGetSymbolAddress((void**)&bufA, g_bufA);
    cudaGetSymbolAddress((void**)&bufB, g_bufB);

    const int smemBytes = (D * D + D * 64) * (int)sizeof(float); // 96 KB
    cudaFuncSetAttribute(gemm_bias_kernel,
                         cudaFuncAttributeMaxDynamicSharedMemorySize, smemBytes);

    const int gemmBlocksV = (N_V + 63) / 64;
    const int gemmBlocksU = (N_U + 63) / 64;
    const int scatBlocks  = (E + 7) / 8;
    const int zeroBlocksU = ((N_U * (D / 4)) + 255) / 256;
    const int zeroBlocksV = ((N_V * (D / 4)) + 255) / 256;

    // Layer 0: Linear on X_v, then v2u
    gemm_bias_kernel<<<gemmBlocksV, 256, smemBytes>>>(X_v, W0, b0, bufA, N_V);
    zero_kernel<<<zeroBlocksU, 256>>>((float4*)bufB, N_U * (D / 4));
    scatter_add_kernel<<<scatBlocks, 256>>>(bufA, bufB, edge_v, edge_u, E);

    // Layer 1: Linear on aggregated U, then u2v
    gemm_bias_kernel<<<gemmBlocksU, 256, smemBytes>>>(bufB, W1, b1, bufA, N_U);
    zero_kernel<<<zeroBlocksV, 256>>>((float4*)bufB, N_V * (D / 4));
    scatter_add_kernel<<<scatBlocks, 256>>>(bufA, bufB, edge_u, edge_v, E);

    // Layer 2: Linear on aggregated V, then v2u into output
    gemm_bias_kernel<<<gemmBlocksV, 256, smemBytes>>>(bufB, W2, b2, bufA, N_V);
    zero_kernel<<<zeroBlocksU, 256>>>((float4*)out, N_U * (D / 4));
    scatter_add_kernel<<<scatBlocks, 256>>>(bufA, out, edge_v, edge_u, E);
}

// round 3
// speedup vs baseline: 1.4914x; 1.4051x over previous
#include <cuda_runtime.h>
#include <cuda_bf16.h>
#include <cstdint>

#define D 128
#define MAXN 50176   // >= max(N_U, N_V)
#define MAXE 640000

typedef unsigned long long u64;

// Scratch (no cudaMalloc allowed).
__device__ float g_bufA[(size_t)MAXN * D];
__device__ float g_bufB[(size_t)MAXN * D];

// CSR structures for the two scatter directions.
__device__ int g_rowptr_u[MAXN + 1];
__device__ int g_rowptr_v[MAXN + 1];
__device__ int g_off_u[MAXN];
__device__ int g_off_v[MAXN];
__device__ int g_srcs_u[MAXE];   // for v2u: source v per dest-u-sorted edge
__device__ int g_srcs_v[MAXE];   // for u2v: source u per dest-v-sorted edge
__device__ int g_bsum_u[64];
__device__ int g_bsum_v[64];

// ---------------------------------------------------------------------------
// Packed fp32x2 helpers
// ---------------------------------------------------------------------------
__device__ __forceinline__ u64 pack2(float a, float b) {
    u64 r; asm("mov.b64 %0, {%1, %2};" : "=l"(r) : "f"(a), "f"(b)); return r;
}
__device__ __forceinline__ void unpack2(u64 v, float& lo, float& hi) {
    asm("mov.b64 {%0, %1}, %2;" : "=f"(lo), "=f"(hi) : "l"(v));
}
__device__ __forceinline__ void ffma2(u64& d, u64 a, u64 b) {
    asm("fma.rn.f32x2 %0, %1, %2, %0;" : "+l"(d) : "l"(a), "l"(b));
}

// ---------------------------------------------------------------------------
// GEMM: Y = X @ W + b  (unchanged from round 2 — known 42.9us)
// ---------------------------------------------------------------------------
__global__ __launch_bounds__(256, 2)
void gemm_bias_kernel(const float* __restrict__ X,
                      const float* __restrict__ W,
                      const float* __restrict__ b,
                      float* __restrict__ Y,
                      int N)
{
    extern __shared__ float smem[];
    float* sW  = smem;            // [128][128]
    float* sXT = smem + D * D;    // [k][row] : [128][64]

    const int tid = threadIdx.x;
    const int rowBase = blockIdx.x * 64;

    {
        const float4* W4 = reinterpret_cast<const float4*>(W);
        float4* sW4 = reinterpret_cast<float4*>(sW);
        #pragma unroll
        for (int i = tid; i < (D * D) / 4; i += 256) sW4[i] = W4[i];
    }
    {
        #pragma unroll
        for (int i = tid; i < 64 * (D / 4); i += 256) {
            int r  = i & 63;
            int k4 = i >> 6;
            float4 v = make_float4(0.f, 0.f, 0.f, 0.f);
            int row = rowBase + r;
            if (row < N)
                v = reinterpret_cast<const float4*>(X + (size_t)row * D)[k4];
            sXT[(k4 * 4 + 0) * 64 + r] = v.x;
            sXT[(k4 * 4 + 1) * 64 + r] = v.y;
            sXT[(k4 * 4 + 2) * 64 + r] = v.z;
            sXT[(k4 * 4 + 3) * 64 + r] = v.w;
        }
    }
    __syncthreads();

    const int lane = tid & 31;
    const int warp = tid >> 5;
    const int wr   = warp * 8;

    u64 acc[4][4];
    {
        const float4 bv = reinterpret_cast<const float4*>(b)[lane];
        #pragma unroll
        for (int rp = 0; rp < 4; rp++) {
            acc[rp][0] = pack2(bv.x, bv.x);
            acc[rp][1] = pack2(bv.y, bv.y);
            acc[rp][2] = pack2(bv.z, bv.z);
            acc[rp][3] = pack2(bv.w, bv.w);
        }
    }

    const float4* sWc = reinterpret_cast<const float4*>(sW) + lane;
    const float*  sx  = sXT + wr;

    #pragma unroll 8
    for (int k = 0; k < D; k++) {
        float4 w = sWc[k * 32];
        u64 wd0 = pack2(w.x, w.x);
        u64 wd1 = pack2(w.y, w.y);
        u64 wd2 = pack2(w.z, w.z);
        u64 wd3 = pack2(w.w, w.w);

        const float* xk = sx + k * 64;
        u64 x0 = *reinterpret_cast<const u64*>(xk + 0);
        u64 x1 = *reinterpret_cast<const u64*>(xk + 2);
        u64 x2 = *reinterpret_cast<const u64*>(xk + 4);
        u64 x3 = *reinterpret_cast<const u64*>(xk + 6);

        ffma2(acc[0][0], x0, wd0); ffma2(acc[0][1], x0, wd1);
        ffma2(acc[0][2], x0, wd2); ffma2(acc[0][3], x0, wd3);
        ffma2(acc[1][0], x1, wd0); ffma2(acc[1][1], x1, wd1);
        ffma2(acc[1][2], x1, wd2); ffma2(acc[1][3], x1, wd3);
        ffma2(acc[2][0], x2, wd0); ffma2(acc[2][1], x2, wd1);
        ffma2(acc[2][2], x2, wd2); ffma2(acc[2][3], x2, wd3);
        ffma2(acc[3][0], x3, wd0); ffma2(acc[3][1], x3, wd1);
        ffma2(acc[3][2], x3, wd2); ffma2(acc[3][3], x3, wd3);
    }

    #pragma unroll
    for (int rp = 0; rp < 4; rp++) {
        int row0 = rowBase + wr + rp * 2;
        float lo0, hi0, lo1, hi1, lo2, hi2, lo3, hi3;
        unpack2(acc[rp][0], lo0, hi0);
        unpack2(acc[rp][1], lo1, hi1);
        unpack2(acc[rp][2], lo2, hi2);
        unpack2(acc[rp][3], lo3, hi3);
        if (row0 < N)
            reinterpret_cast<float4*>(Y + (size_t)row0 * D)[lane] =
                make_float4(lo0, lo1, lo2, lo3);
        if (row0 + 1 < N)
            reinterpret_cast<float4*>(Y + (size_t)(row0 + 1) * D)[lane] =
                make_float4(hi0, hi1, hi2, hi3);
    }
}

// ---------------------------------------------------------------------------
// CSR build: counting sort of edges by destination.
// ---------------------------------------------------------------------------
__global__ __launch_bounds__(256)
void zero_int_kernel(int* __restrict__ p, int n)
{
    int i = blockIdx.x * blockDim.x + threadIdx.x;
    int stride = gridDim.x * blockDim.x;
    for (; i < n; i += stride) p[i] = 0;
}

__global__ __launch_bounds__(256)
void hist_kernel(const int* __restrict__ dest, int E, int* __restrict__ cnt)
{
    int i = blockIdx.x * blockDim.x + threadIdx.x;
    int stride = gridDim.x * blockDim.x;
    for (; i < E; i += stride) atomicAdd(&cnt[dest[i]], 1);
}

// Pass A: per-block exclusive scan of cnt into rowptr (no cross-block offset),
// block sums to bsum. Block size 1024, 1024 items per block.
__global__ __launch_bounds__(1024)
void scanA_kernel(const int* __restrict__ cnt, int* __restrict__ rowptr,
                  int* __restrict__ bsum, int n)
{
    __shared__ int s[1024];
    int t = threadIdx.x;
    int i = blockIdx.x * 1024 + t;
    int x = (i < n) ? cnt[i] : 0;
    s[t] = x;
    __syncthreads();
    // Hillis-Steele inclusive scan
    #pragma unroll
    for (int off = 1; off < 1024; off <<= 1) {
        int v = (t >= off) ? s[t - off] : 0;
        __syncthreads();
        s[t] += v;
        __syncthreads();
    }
    if (i < n) rowptr[i] = s[t] - x;           // exclusive
    if (t == 1023) bsum[blockIdx.x] = s[1023]; // block total
}

// Pass B: exclusive scan of block sums (small; single thread is fine).
__global__ void scanB_kernel(int* __restrict__ bsum, int nb)
{
    if (threadIdx.x == 0 && blockIdx.x == 0) {
        int run = 0;
        for (int i = 0; i < nb; i++) { int v = bsum[i]; bsum[i] = run; run += v; }
    }
}

// Pass C: add block offsets; copy to running-offset array; set rowptr[n].
__global__ __launch_bounds__(1024)
void scanC_kernel(int* __restrict__ rowptr, int* __restrict__ off,
                  const int* __restrict__ bsum, int n, int E)
{
    int t = threadIdx.x;
    int i = blockIdx.x * 1024 + t;
    if (i < n) {
        int r = rowptr[i] + bsum[blockIdx.x];
        rowptr[i] = r;
        off[i] = r;
    }
    if (i == 0) rowptr[n] = E;
}

__global__ __launch_bounds__(256)
void fill_kernel(const int* __restrict__ dest, const int* __restrict__ src,
                 int E, int* __restrict__ off, int* __restrict__ srcs)
{
    int i = blockIdx.x * blockDim.x + threadIdx.x;
    int stride = gridDim.x * blockDim.x;
    for (; i < E; i += stride) {
        int d = dest[i];
        int p = atomicAdd(&off[d], 1);
        srcs[p] = src[i];
    }
}

// ---------------------------------------------------------------------------
// CSR aggregation: dst[d] = sum over segment of src rows. One warp per dest.
// No atomics; writes every row (zero for empty segments).
// ---------------------------------------------------------------------------
__global__ __launch_bounds__(256)
void csr_aggregate_kernel(const float* __restrict__ src,
                          float* __restrict__ dst,
                          const int* __restrict__ rowptr,
                          const int* __restrict__ srcs,
                          int N)
{
    int d = blockIdx.x * 8 + (threadIdx.x >> 5);
    if (d >= N) return;
    int lane = threadIdx.x & 31;

    int beg = __ldg(&rowptr[d]);
    int end = __ldg(&rowptr[d + 1]);

    float4 acc = make_float4(0.f, 0.f, 0.f, 0.f);

    int i = beg;
    for (; i + 4 <= end; i += 4) {
        int s0 = __ldg(&srcs[i + 0]);
        int s1 = __ldg(&srcs[i + 1]);
        int s2 = __ldg(&srcs[i + 2]);
        int s3 = __ldg(&srcs[i + 3]);
        float4 a = __ldg(reinterpret_cast<const float4*>(src + (size_t)s0 * D) + lane);
        float4 b = __ldg(reinterpret_cast<const float4*>(src + (size_t)s1 * D) + lane);
        float4 c = __ldg(reinterpret_cast<const float4*>(src + (size_t)s2 * D) + lane);
        float4 e = __ldg(reinterpret_cast<const float4*>(src + (size_t)s3 * D) + lane);
        acc.x += (a.x + b.x) + (c.x + e.x);
        acc.y += (a.y + b.y) + (c.y + e.y);
        acc.z += (a.z + b.z) + (c.z + e.z);
        acc.w += (a.w + b.w) + (c.w + e.w);
    }
    for (; i < end; i++) {
        int s0 = __ldg(&srcs[i]);
        float4 a = __ldg(reinterpret_cast<const float4*>(src + (size_t)s0 * D) + lane);
        acc.x += a.x; acc.y += a.y; acc.z += a.z; acc.w += a.w;
    }

    reinterpret_cast<float4*>(dst + (size_t)d * D)[lane] = acc;
}

// ---------------------------------------------------------------------------
static void build_csr(const int* dest, const int* src, int E, int N,
                      int* rowptr, int* off, int* srcs, int* bsum)
{
    const int nb = (N + 1023) / 1024;
    zero_int_kernel<<<(N + 255) / 256, 256>>>(off, N);
    hist_kernel<<<256, 256>>>(dest, E, off);
    scanA_kernel<<<nb, 1024>>>(off, rowptr, bsum, N);
    scanB_kernel<<<1, 32>>>(bsum, nb);
    scanC_kernel<<<nb, 1024>>>(rowptr, off, bsum, N, E);
    fill_kernel<<<512, 256>>>(dest, src, E, off, srcs);
}

extern "C" void kernel_launch(void* const* d_in, const int* in_sizes, int n_in,
                              void* d_out, int out_size)
{
    const float* X_v    = (const float*)d_in[1];
    const int*   edge_u = (const int*)  d_in[2];
    const int*   edge_v = (const int*)  d_in[3];
    const float* W0     = (const float*)d_in[4];
    const float* b0     = (const float*)d_in[5];
    const float* W1     = (const float*)d_in[6];
    const float* b1     = (const float*)d_in[7];
    const float* W2     = (const float*)d_in[8];
    const float* b2     = (const float*)d_in[9];
    float*       out    = (float*)d_out;

    const int N_V = in_sizes[1] / D;
    const int E   = in_sizes[2];
    const int N_U = out_size / D;

    float *bufA, *bufB;
    cudaGetSymbolAddress((void**)&bufA, g_bufA);
    cudaGetSymbolAddress((void**)&bufB, g_bufB);
    int *rowptr_u, *rowptr_v, *off_u, *off_v, *srcs_u, *srcs_v, *bsum_u, *bsum_v;
    cudaGetSymbolAddress((void**)&rowptr_u, g_rowptr_u);
    cudaGetSymbolAddress((void**)&rowptr_v, g_rowptr_v);
    cudaGetSymbolAddress((void**)&off_u, g_off_u);
    cudaGetSymbolAddress((void**)&off_v, g_off_v);
    cudaGetSymbolAddress((void**)&srcs_u, g_srcs_u);
    cudaGetSymbolAddress((void**)&srcs_v, g_srcs_v);
    cudaGetSymbolAddress((void**)&bsum_u, g_bsum_u);
    cudaGetSymbolAddress((void**)&bsum_v, g_bsum_v);

    const int smemBytes = (D * D + D * 64) * (int)sizeof(float); // 96 KB
    cudaFuncSetAttribute(gemm_bias_kernel,
                         cudaFuncAttributeMaxDynamicSharedMemorySize, smemBytes);

    // Build both CSRs up front (independent of feature data).
    build_csr(edge_u, edge_v, E, N_U, rowptr_u, off_u, srcs_u, bsum_u); // v2u
    build_csr(edge_v, edge_u, E, N_V, rowptr_v, off_v, srcs_v, bsum_v); // u2v

    const int gemmBlocksV = (N_V + 63) / 64;
    const int gemmBlocksU = (N_U + 63) / 64;
    const int aggBlocksU  = (N_U + 7) / 8;
    const int aggBlocksV  = (N_V + 7) / 8;

    // Layer 0: Linear on X_v, then v2u
    gemm_bias_kernel<<<gemmBlocksV, 256, smemBytes>>>(X_v, W0, b0, bufA, N_V);
    csr_aggregate_kernel<<<aggBlocksU, 256>>>(bufA, bufB, rowptr_u, srcs_u, N_U);

    // Layer 1: Linear on aggregated U, then u2v
    gemm_bias_kernel<<<gemmBlocksU, 256, smemBytes>>>(bufB, W1, b1, bufA, N_U);
    csr_aggregate_kernel<<<aggBlocksV, 256>>>(bufA, bufB, rowptr_v, srcs_v, N_V);

    // Layer 2: Linear on aggregated V, then v2u into output
    gemm_bias_kernel<<<gemmBlocksV, 256, smemBytes>>>(bufB, W2, b2, bufA, N_V);
    csr_aggregate_kernel<<<aggBlocksU, 256>>>(bufA, out, rowptr_u, srcs_u, N_U);
}

// round 5
// speedup vs baseline: 1.6958x; 1.1370x over previous
#include <cuda_runtime.h>
#include <cuda_bf16.h>
#include <cstdint>

#define D 128
#define MAXN 50176   // >= max(N_U, N_V)
#define MAXE 640000

typedef unsigned long long u64;

// ---------------------------------------------------------------------------
// Scratch (no cudaMalloc allowed).
// ---------------------------------------------------------------------------
__device__ float         g_bufY[(size_t)MAXN * D];     // GEMM output (fp32)
__device__ __nv_bfloat16 g_hi[(size_t)MAXN * D];       // split inputs for GEMM
__device__ __nv_bfloat16 g_lo[(size_t)MAXN * D];
__device__ __nv_bfloat16 g_wthi[3 * D * D];            // W^T splits [j][k]
__device__ __nv_bfloat16 g_wtlo[3 * D * D];

// CSR structures for the two scatter directions.
__device__ int g_rowptr_u[MAXN + 1];
__device__ int g_rowptr_v[MAXN + 1];
__device__ int g_off_u[MAXN];
__device__ int g_off_v[MAXN];
__device__ int g_srcs_u[MAXE];
__device__ int g_srcs_v[MAXE];
__device__ int g_bsum_u[64];
__device__ int g_bsum_v[64];

// ---------------------------------------------------------------------------
// mma.sync / ldmatrix helpers (baseline PTX, works on compute_103)
// ---------------------------------------------------------------------------
__device__ __forceinline__ uint32_t smem_u32(const void* p) {
    uint32_t a;
    asm("{ .reg .u64 t; cvta.to.shared.u64 t, %1; cvt.u32.u64 %0, t; }" : "=r"(a) : "l"(p));
    return a;
}

__device__ __forceinline__ void ldm_x4(uint32_t (&r)[4], uint32_t addr) {
    asm volatile("ldmatrix.sync.aligned.m8n8.x4.shared.b16 {%0,%1,%2,%3}, [%4];"
                 : "=r"(r[0]), "=r"(r[1]), "=r"(r[2]), "=r"(r[3]) : "r"(addr));
}

__device__ __forceinline__ void mma_bf16(float (&c)[4], const uint32_t (&a)[4],
                                         uint32_t b0, uint32_t b1) {
    asm volatile(
        "mma.sync.aligned.m16n8k16.row.col.f32.bf16.bf16.f32 "
        "{%0,%1,%2,%3}, {%4,%5,%6,%7}, {%8,%9}, {%0,%1,%2,%3};"
        : "+f"(c[0]), "+f"(c[1]), "+f"(c[2]), "+f"(c[3])
        : "r"(a[0]), "r"(a[1]), "r"(a[2]), "r"(a[3]), "r"(b0), "r"(b1));
}

// ---------------------------------------------------------------------------
// Tensor GEMM: Y[64-row tile] = A @ W^T + bias, bf16 3-pass split, fp32 accum.
// Block: 128 threads (4 warps). Warp w: rows w*16..w*16+15, all 128 cols.
// smem layouts (bf16, row stride 136 elements = 272B, conflict-free ldmatrix):
//   A tiles  [64][136]  x2 (hi, lo)
//   B tiles  [128][136] x2 (hi, lo)   B = W^T stored [n][k]
// ---------------------------------------------------------------------------
#define STR 136           // smem row stride in bf16 elements
#define SM_BIAS 0                        // 512B
#define SM_AHI  512                      // 64*272 = 17408
#define SM_ALO  (SM_AHI + 64 * 272)      // 17920
#define SM_BHI  (SM_ALO + 64 * 272)      // 35328
#define SM_BLO  (SM_BHI + 128 * 272)     // 70144
#define SM_TOT  (SM_BLO + 128 * 272)     // 104960
#define SM_EP   512                      // epilogue reuse over A area
#define EPSTR   132                      // fp32 row stride (528B, 16B aligned)

__global__ __launch_bounds__(128, 2)
void gemm_tc_kernel(const __nv_bfloat16* __restrict__ Ahi,
                    const __nv_bfloat16* __restrict__ Alo,
                    const __nv_bfloat16* __restrict__ Bhi,
                    const __nv_bfloat16* __restrict__ Blo,
                    const float* __restrict__ bias,
                    float* __restrict__ Y,
                    int N)
{
    extern __shared__ char smem[];
    const uint32_t sb = smem_u32(smem);
    const int tid  = threadIdx.x;
    const int lane = tid & 31;
    const int warp = tid >> 5;
    const int rowBase = blockIdx.x * 64;

    // bias
    ((float*)(smem + SM_BIAS))[tid] = bias[tid];

    // stage B = W^T (hi, lo): 128 rows x 16 chunks of 16B
    #pragma unroll 4
    for (int i = tid; i < 128 * 16; i += 128) {
        int n = i >> 4, c = i & 15;
        uint32_t so = (uint32_t)(n * 272 + c * 16);
        *(uint4*)(smem + SM_BHI + so) = *(const uint4*)(Bhi + (size_t)n * D + c * 8);
        *(uint4*)(smem + SM_BLO + so) = *(const uint4*)(Blo + (size_t)n * D + c * 8);
    }
    // stage A (hi, lo): 64 rows x 16 chunks (zero-pad OOB rows)
    #pragma unroll 4
    for (int i = tid; i < 64 * 16; i += 128) {
        int r = i >> 4, c = i & 15;
        int row = rowBase + r;
        uint4 vh = make_uint4(0, 0, 0, 0), vl = vh;
        if (row < N) {
            vh = *(const uint4*)(Ahi + (size_t)row * D + c * 8);
            vl = *(const uint4*)(Alo + (size_t)row * D + c * 8);
        }
        uint32_t so = (uint32_t)(r * 272 + c * 16);
        *(uint4*)(smem + SM_AHI + so) = vh;
        *(uint4*)(smem + SM_ALO + so) = vl;
    }
    __syncthreads();

    // accumulators: 16 n-tiles of m16n8, 4 floats each
    float acc[16][4];
    #pragma unroll
    for (int t = 0; t < 16; t++) {
        acc[t][0] = 0.f; acc[t][1] = 0.f; acc[t][2] = 0.f; acc[t][3] = 0.f;
    }

    // per-lane ldmatrix address components
    const int wr = warp * 16;
    const uint32_t aRowOff = (uint32_t)((wr + (lane & 15)) * STR + ((lane >> 4) << 3)) * 2;
    const int nOff  = (lane & 7) + ((lane >> 4) & 1) * 8;
    const int kHalf = ((lane >> 3) & 1) * 8;
    const uint32_t bRowOff = (uint32_t)(nOff * STR + kHalf) * 2;

    #pragma unroll 1
    for (int pass = 0; pass < 3; pass++) {
        uint32_t aBase = sb + ((pass == 2) ? SM_ALO : SM_AHI) + aRowOff;
        uint32_t bBase = sb + ((pass == 1) ? SM_BLO : SM_BHI) + bRowOff;
        #pragma unroll 2
        for (int k0 = 0; k0 < 128; k0 += 16) {
            uint32_t a[4];
            ldm_x4(a, aBase + k0 * 2);
            #pragma unroll
            for (int j = 0; j < 8; j++) {
                uint32_t b[4];
                ldm_x4(b, bBase + (uint32_t)(j * 16 * STR + k0) * 2);
                mma_bf16(acc[2 * j],     a, b[0], b[1]);
                mma_bf16(acc[2 * j + 1], a, b[2], b[3]);
            }
        }
    }
    __syncthreads();   // before overwriting A area with epilogue

    // epilogue: frags -> smem (fp32), then coalesced +bias write to gmem
    {
        float* ep = (float*)(smem + SM_EP);
        const int r0 = wr + (lane >> 2);
        const int cq = 2 * (lane & 3);
        #pragma unroll
        for (int t = 0; t < 16; t++) {
            int col = t * 8 + cq;
            *(float2*)(ep + r0 * EPSTR + col)       = make_float2(acc[t][0], acc[t][1]);
            *(float2*)(ep + (r0 + 8) * EPSTR + col) = make_float2(acc[t][2], acc[t][3]);
        }
    }
    __syncthreads();
    {
        const float*  ep = (const float*)(smem + SM_EP);
        const float4* bs = (const float4*)(smem + SM_BIAS);
        #pragma unroll 4
        for (int i = tid; i < 64 * 32; i += 128) {
            int r = i >> 5, c4 = i & 31;
            int row = rowBase + r;
            if (row < N) {
                float4 v = *(const float4*)(ep + r * EPSTR + c4 * 4);
                float4 bb = bs[c4];
                v.x += bb.x; v.y += bb.y; v.z += bb.z; v.w += bb.w;
                *(float4*)(Y + (size_t)row * D + c4 * 4) = v;
            }
        }
    }
}

// ---------------------------------------------------------------------------
// Split fp32 -> (bf16 hi, bf16 lo)
// ---------------------------------------------------------------------------
__device__ __forceinline__ void bf16_split(float f, __nv_bfloat16& h, __nv_bfloat16& l) {
    h = __float2bfloat16(f);
    l = __float2bfloat16(f - __bfloat162float(h));
}

__global__ __launch_bounds__(256)
void split_kernel(const float* __restrict__ X,
                  __nv_bfloat16* __restrict__ hi,
                  __nv_bfloat16* __restrict__ lo, int n)
{
    int i = blockIdx.x * blockDim.x + threadIdx.x;
    int stride = gridDim.x * blockDim.x;
    for (; i < n; i += stride) {
        __nv_bfloat16 h, l;
        bf16_split(X[i], h, l);
        hi[i] = h; lo[i] = l;
    }
}

// W^T splits for all three weights: WT[w][j*128+k] = W_w[k*128+j]
__global__ __launch_bounds__(256)
void wt_split_kernel(const float* __restrict__ W0,
                     const float* __restrict__ W1,
                     const float* __restrict__ W2,
                     __nv_bfloat16* __restrict__ hi,
                     __nv_bfloat16* __restrict__ lo)
{
    int i = blockIdx.x * blockDim.x + threadIdx.x;
    int stride = gridDim.x * blockDim.x;
    for (; i < 3 * D * D; i += stride) {
        int w = i / (D * D);
        int rem = i - w * (D * D);
        int j = rem >> 7, k = rem & 127;
        const float* W = (w == 0) ? W0 : (w == 1) ? W1 : W2;
        __nv_bfloat16 h, l;
        bf16_split(W[k * D + j], h, l);
        hi[i] = h; lo[i] = l;
    }
}

// ---------------------------------------------------------------------------
// CSR build (counting sort by destination).
// ---------------------------------------------------------------------------
__global__ __launch_bounds__(256)
void zero_int_kernel(int* __restrict__ p, int n)
{
    int i = blockIdx.x * blockDim.x + threadIdx.x;
    int stride = gridDim.x * blockDim.x;
    for (; i < n; i += stride) p[i] = 0;
}

__global__ __launch_bounds__(256)
void hist_kernel(const int* __restrict__ dest, int E, int* __restrict__ cnt)
{
    int i = blockIdx.x * blockDim.x + threadIdx.x;
    int stride = gridDim.x * blockDim.x;
    for (; i < E; i += stride) atomicAdd(&cnt[dest[i]], 1);
}

__global__ __launch_bounds__(1024)
void scanA_kernel(const int* __restrict__ cnt, int* __restrict__ rowptr,
                  int* __restrict__ bsum, int n)
{
    __shared__ int s[1024];
    int t = threadIdx.x;
    int i = blockIdx.x * 1024 + t;
    int x = (i < n) ? cnt[i] : 0;
    s[t] = x;
    __syncthreads();
    #pragma unroll
    for (int off = 1; off < 1024; off <<= 1) {
        int v = (t >= off) ? s[t - off] : 0;
        __syncthreads();
        s[t] += v;
        __syncthreads();
    }
    if (i < n) rowptr[i] = s[t] - x;
    if (t == 1023) bsum[blockIdx.x] = s[1023];
}

__global__ void scanB_kernel(int* __restrict__ bsum, int nb)
{
    __shared__ int s[64];
    int t = threadIdx.x;
    int v = (t < nb) ? bsum[t] : 0;
    s[t] = v;
    __syncthreads();
    #pragma unroll
    for (int off = 1; off < 64; off <<= 1) {
        int x = (t >= off) ? s[t - off] : 0;
        __syncthreads();
        s[t] += x;
        __syncthreads();
    }
    if (t < nb) bsum[t] = s[t] - v;
}

__global__ __launch_bounds__(1024)
void scanC_kernel(int* __restrict__ rowptr, int* __restrict__ off,
                  const int* __restrict__ bsum, int n, int E)
{
    int t = threadIdx.x;
    int i = blockIdx.x * 1024 + t;
    if (i < n) {
        int r = rowptr[i] + bsum[blockIdx.x];
        rowptr[i] = r;
        off[i] = r;
    }
    if (i == 0) rowptr[n] = E;
}

__global__ __launch_bounds__(256)
void fill_kernel(const int* __restrict__ dest, const int* __restrict__ src,
                 int E, int* __restrict__ off, int* __restrict__ srcs)
{
    int i = blockIdx.x * blockDim.x + threadIdx.x;
    int stride = gridDim.x * blockDim.x;
    for (; i < E; i += stride) {
        int d = dest[i];
        int p = atomicAdd(&off[d], 1);
        srcs[p] = src[i];
    }
}

// ---------------------------------------------------------------------------
// CSR aggregation. One warp per dest row; fp32 accumulation.
// ---------------------------------------------------------------------------
__device__ __forceinline__ float4 csr_gather_row(const float* __restrict__ src,
                                                 const int* __restrict__ srcs,
                                                 int beg, int end, int lane)
{
    float4 acc = make_float4(0.f, 0.f, 0.f, 0.f);
    int i = beg;
    for (; i + 4 <= end; i += 4) {
        int s0 = __ldg(&srcs[i + 0]);
        int s1 = __ldg(&srcs[i + 1]);
        int s2 = __ldg(&srcs[i + 2]);
        int s3 = __ldg(&srcs[i + 3]);
        float4 a = __ldg(reinterpret_cast<const float4*>(src + (size_t)s0 * D) + lane);
        float4 b = __ldg(reinterpret_cast<const float4*>(src + (size_t)s1 * D) + lane);
        float4 c = __ldg(reinterpret_cast<const float4*>(src + (size_t)s2 * D) + lane);
        float4 e = __ldg(reinterpret_cast<const float4*>(src + (size_t)s3 * D) + lane);
        acc.x += (a.x + b.x) + (c.x + e.x);
        acc.y += (a.y + b.y) + (c.y + e.y);
        acc.z += (a.z + b.z) + (c.z + e.z);
        acc.w += (a.w + b.w) + (c.w + e.w);
    }
    for (; i < end; i++) {
        int s0 = __ldg(&srcs[i]);
        float4 a = __ldg(reinterpret_cast<const float4*>(src + (size_t)s0 * D) + lane);
        acc.x += a.x; acc.y += a.y; acc.z += a.z; acc.w += a.w;
    }
    return acc;
}

__global__ __launch_bounds__(256)
void csr_aggregate_split_kernel(const float* __restrict__ src,
                                __nv_bfloat16* __restrict__ dhi,
                                __nv_bfloat16* __restrict__ dlo,
                                const int* __restrict__ rowptr,
                                const int* __restrict__ srcs,
                                int N)
{
    int d = blockIdx.x * 8 + (threadIdx.x >> 5);
    if (d >= N) return;
    int lane = threadIdx.x & 31;
    float4 acc = csr_gather_row(src, srcs, __ldg(&rowptr[d]), __ldg(&rowptr[d + 1]), lane);

    __nv_bfloat16 h0, l0, h1, l1, h2, l2, h3, l3;
    bf16_split(acc.x, h0, l0); bf16_split(acc.y, h1, l1);
    bf16_split(acc.z, h2, l2); bf16_split(acc.w, h3, l3);
    __nv_bfloat162 hi01 = __nv_bfloat162(h0, h1), hi23 = __nv_bfloat162(h2, h3);
    __nv_bfloat162 lo01 = __nv_bfloat162(l0, l1), lo23 = __nv_bfloat162(l2, l3);
    uint2 hv, lv;
    hv.x = *(uint32_t*)&hi01; hv.y = *(uint32_t*)&hi23;
    lv.x = *(uint32_t*)&lo01; lv.y = *(uint32_t*)&lo23;
    *(uint2*)(dhi + (size_t)d * D + lane * 4) = hv;
    *(uint2*)(dlo + (size_t)d * D + lane * 4) = lv;
}

__global__ __launch_bounds__(256)
void csr_aggregate_f32_kernel(const float* __restrict__ src,
                              float* __restrict__ dst,
                              const int* __restrict__ rowptr,
                              const int* __restrict__ srcs,
                              int N)
{
    int d = blockIdx.x * 8 + (threadIdx.x >> 5);
    if (d >= N) return;
    int lane = threadIdx.x & 31;
    float4 acc = csr_gather_row(src, srcs, __ldg(&rowptr[d]), __ldg(&rowptr[d + 1]), lane);
    reinterpret_cast<float4*>(dst + (size_t)d * D)[lane] = acc;
}

// ---------------------------------------------------------------------------
static void build_csr(const int* dest, const int* src, int E, int N,
                      int* rowptr, int* off, int* srcs, int* bsum)
{
    const int nb = (N + 1023) / 1024;
    zero_int_kernel<<<(N + 255) / 256, 256>>>(off, N);
    hist_kernel<<<256, 256>>>(dest, E, off);
    scanA_kernel<<<nb, 1024>>>(off, rowptr, bsum, N);
    scanB_kernel<<<1, 64>>>(bsum, nb);
    scanC_kernel<<<nb, 1024>>>(rowptr, off, bsum, N, E);
    fill_kernel<<<512, 256>>>(dest, src, E, off, srcs);
}

extern "C" void kernel_launch(void* const* d_in, const int* in_sizes, int n_in,
                              void* d_out, int out_size)
{
    const float* X_v    = (const float*)d_in[1];
    const int*   edge_u = (const int*)  d_in[2];
    const int*   edge_v = (const int*)  d_in[3];
    const float* W0     = (const float*)d_in[4];
    const float* b0     = (const float*)d_in[5];
    const float* W1     = (const float*)d_in[6];
    const float* b1     = (const float*)d_in[7];
    const float* W2     = (const float*)d_in[8];
    const float* b2     = (const float*)d_in[9];
    float*       out    = (float*)d_out;

    const int N_V = in_sizes[1] / D;
    const int E   = in_sizes[2];
    const int N_U = out_size / D;

    float* bufY; __nv_bfloat16 *hi, *lo, *wthi, *wtlo;
    cudaGetSymbolAddress((void**)&bufY, g_bufY);
    cudaGetSymbolAddress((void**)&hi,   g_hi);
    cudaGetSymbolAddress((void**)&lo,   g_lo);
    cudaGetSymbolAddress((void**)&wthi, g_wthi);
    cudaGetSymbolAddress((void**)&wtlo, g_wtlo);
    int *rowptr_u, *rowptr_v, *off_u, *off_v, *srcs_u, *srcs_v, *bsum_u, *bsum_v;
    cudaGetSymbolAddress((void**)&rowptr_u, g_rowptr_u);
    cudaGetSymbolAddress((void**)&rowptr_v, g_rowptr_v);
    cudaGetSymbolAddress((void**)&off_u, g_off_u);
    cudaGetSymbolAddress((void**)&off_v, g_off_v);
    cudaGetSymbolAddress((void**)&srcs_u, g_srcs_u);
    cudaGetSymbolAddress((void**)&srcs_v, g_srcs_v);
    cudaGetSymbolAddress((void**)&bsum_u, g_bsum_u);
    cudaGetSymbolAddress((void**)&bsum_v, g_bsum_v);

    cudaFuncSetAttribute(gemm_tc_kernel,
                         cudaFuncAttributeMaxDynamicSharedMemorySize, SM_TOT);

    // CSR builds (independent of feature data)
    build_csr(edge_u, edge_v, E, N_U, rowptr_u, off_u, srcs_u, bsum_u); // v2u
    build_csr(edge_v, edge_u, E, N_V, rowptr_v, off_v, srcs_v, bsum_v); // u2v

    // Weight transposes + splits; X_v split
    wt_split_kernel<<<(3 * D * D + 255) / 256, 256>>>(W0, W1, W2, wthi, wtlo);
    split_kernel<<<1024, 256>>>(X_v, hi, lo, N_V * D);

    const int gemmBlocksV = (N_V + 63) / 64;
    const int gemmBlocksU = (N_U + 63) / 64;
    const int aggBlocksU  = (N_U + 7) / 8;
    const int aggBlocksV  = (N_V + 7) / 8;

    // Layer 0: Y = X_v @ W0 + b0 ; v2u aggregate -> split
    gemm_tc_kernel<<<gemmBlocksV, 128, SM_TOT>>>(hi, lo, wthi, wtlo, b0, bufY, N_V);
    csr_aggregate_split_kernel<<<aggBlocksU, 256>>>(bufY, hi, lo, rowptr_u, srcs_u, N_U);

    // Layer 1: Y = agg @ W1 + b1 ; u2v aggregate -> split
    gemm_tc_kernel<<<gemmBlocksU, 128, SM_TOT>>>(hi, lo, wthi + D * D, wtlo + D * D, b1, bufY, N_U);
    csr_aggregate_split_kernel<<<aggBlocksV, 256>>>(bufY, hi, lo, rowptr_v, srcs_v, N_V);

    // Layer 2: Y = agg @ W2 + b2 ; v2u aggregate -> out (fp32)
    gemm_tc_kernel<<<gemmBlocksV, 128, SM_TOT>>>(hi, lo, wthi + 2 * D * D, wtlo + 2 * D * D, b2, bufY, N_V);
    csr_aggregate_f32_kernel<<<aggBlocksU, 256>>>(bufY, out, rowptr_u, srcs_u, N_U);
}

// round 6
// speedup vs baseline: 1.8736x; 1.1049x over previous
#include <cuda_runtime.h>
#include <cuda_bf16.h>
#include <cstdint>

#define D 128
#define MAXN 50176
#define MAXE 640000

typedef unsigned long long u64;

// ---------------------------------------------------------------------------
// Scratch (no cudaMalloc allowed).
// ---------------------------------------------------------------------------
__device__ float         g_bufY[(size_t)MAXN * D];   // S_u = v2u(X_v)
__device__ float         g_bufZ[(size_t)MAXN * D];   // T_v = u2v(S_u)
__device__ __nv_bfloat16 g_hi[(size_t)MAXN * D];     // R split hi
__device__ __nv_bfloat16 g_lo[(size_t)MAXN * D];     // R split lo
__device__ float         g_P[D * D];                 // W1@W2
__device__ float         g_W012[D * D];              // W0@W1@W2
__device__ __nv_bfloat16 g_wthi[D * D];              // (W012)^T split
__device__ __nv_bfloat16 g_wtlo[D * D];
__device__ float         g_g1[D];                    // b0@W1@W2
__device__ float         g_g2[D];                    // b1@W2
__device__ float         g_du[MAXN];
__device__ float         g_dv[MAXN];
__device__ float         g_ev[MAXN];                 // u2v(d_u)
__device__ float         g_c1[MAXN];                 // v2u(e_v)
__device__ float         g_c2[MAXN];                 // v2u(d_v)

// CSR structures.
__device__ int g_rowptr_u[MAXN + 1];
__device__ int g_rowptr_v[MAXN + 1];
__device__ int g_off_u[MAXN];
__device__ int g_off_v[MAXN];
__device__ int g_srcs_u[MAXE];
__device__ int g_srcs_v[MAXE];
__device__ int g_bsum_u[64];
__device__ int g_bsum_v[64];

// ---------------------------------------------------------------------------
// mma.sync / ldmatrix helpers (baseline PTX, works on compute_103)
// ---------------------------------------------------------------------------
__device__ __forceinline__ uint32_t smem_u32(const void* p) {
    uint32_t a;
    asm("{ .reg .u64 t; cvta.to.shared.u64 t, %1; cvt.u32.u64 %0, t; }" : "=r"(a) : "l"(p));
    return a;
}

__device__ __forceinline__ void ldm_x4(uint32_t (&r)[4], uint32_t addr) {
    asm volatile("ldmatrix.sync.aligned.m8n8.x4.shared.b16 {%0,%1,%2,%3}, [%4];"
                 : "=r"(r[0]), "=r"(r[1]), "=r"(r[2]), "=r"(r[3]) : "r"(addr));
}

__device__ __forceinline__ void mma_bf16(float (&c)[4], const uint32_t (&a)[4],
                                         uint32_t b0, uint32_t b1) {
    asm volatile(
        "mma.sync.aligned.m16n8k16.row.col.f32.bf16.bf16.f32 "
        "{%0,%1,%2,%3}, {%4,%5,%6,%7}, {%8,%9}, {%0,%1,%2,%3};"
        : "+f"(c[0]), "+f"(c[1]), "+f"(c[2]), "+f"(c[3])
        : "r"(a[0]), "r"(a[1]), "r"(a[2]), "r"(a[3]), "r"(b0), "r"(b1));
}

__device__ __forceinline__ void bf16_split(float f, __nv_bfloat16& h, __nv_bfloat16& l) {
    h = __float2bfloat16(f);
    l = __float2bfloat16(f - __bfloat162float(h));
}

// ---------------------------------------------------------------------------
// Final tensor GEMM: out[64-row tile] = R @ W012 + c1*g1 + c2*g2 + du*g3
// bf16 3-pass split (hi*hi + hi*lo + lo*hi), fp32 accum. 4 warps.
// ---------------------------------------------------------------------------
#define STR 136
#define SM_G1   0                        // 512B
#define SM_G2   512
#define SM_G3   1024
#define SM_AHI  1536
#define SM_ALO  (SM_AHI + 64 * 272)      // +17408
#define SM_BHI  (SM_ALO + 64 * 272)
#define SM_BLO  (SM_BHI + 128 * 272)     // +34816
#define SM_TOT  (SM_BLO + 128 * 272)     // 105984
#define SM_EP   1536
#define EPSTR   132

__global__ __launch_bounds__(128, 2)
void gemm_final_kernel(const __nv_bfloat16* __restrict__ Ahi,
                       const __nv_bfloat16* __restrict__ Alo,
                       const __nv_bfloat16* __restrict__ Bhi,
                       const __nv_bfloat16* __restrict__ Blo,
                       const float* __restrict__ g1,
                       const float* __restrict__ g2,
                       const float* __restrict__ g3,
                       const float* __restrict__ c1,
                       const float* __restrict__ c2,
                       const float* __restrict__ du,
                       float* __restrict__ Y,
                       int N)
{
    extern __shared__ char smem[];
    const uint32_t sb = smem_u32(smem);
    const int tid  = threadIdx.x;
    const int lane = tid & 31;
    const int warp = tid >> 5;
    const int rowBase = blockIdx.x * 64;

    ((float*)(smem + SM_G1))[tid] = g1[tid];
    ((float*)(smem + SM_G2))[tid] = g2[tid];
    ((float*)(smem + SM_G3))[tid] = g3[tid];

    #pragma unroll 4
    for (int i = tid; i < 128 * 16; i += 128) {
        int n = i >> 4, c = i & 15;
        uint32_t so = (uint32_t)(n * 272 + c * 16);
        *(uint4*)(smem + SM_BHI + so) = *(const uint4*)(Bhi + (size_t)n * D + c * 8);
        *(uint4*)(smem + SM_BLO + so) = *(const uint4*)(Blo + (size_t)n * D + c * 8);
    }
    #pragma unroll 4
    for (int i = tid; i < 64 * 16; i += 128) {
        int r = i >> 4, c = i & 15;
        int row = rowBase + r;
        uint4 vh = make_uint4(0, 0, 0, 0), vl = vh;
        if (row < N) {
            vh = *(const uint4*)(Ahi + (size_t)row * D + c * 8);
            vl = *(const uint4*)(Alo + (size_t)row * D + c * 8);
        }
        uint32_t so = (uint32_t)(r * 272 + c * 16);
        *(uint4*)(smem + SM_AHI + so) = vh;
        *(uint4*)(smem + SM_ALO + so) = vl;
    }
    __syncthreads();

    float acc[16][4];
    #pragma unroll
    for (int t = 0; t < 16; t++) {
        acc[t][0] = 0.f; acc[t][1] = 0.f; acc[t][2] = 0.f; acc[t][3] = 0.f;
    }

    const int wr = warp * 16;
    const uint32_t aRowOff = (uint32_t)((wr + (lane & 15)) * STR + ((lane >> 4) << 3)) * 2;
    const int nOff  = (lane & 7) + ((lane >> 4) & 1) * 8;
    const int kHalf = ((lane >> 3) & 1) * 8;
    const uint32_t bRowOff = (uint32_t)(nOff * STR + kHalf) * 2;

    #pragma unroll 1
    for (int pass = 0; pass < 3; pass++) {
        uint32_t aBase = sb + ((pass == 2) ? SM_ALO : SM_AHI) + aRowOff;
        uint32_t bBase = sb + ((pass == 1) ? SM_BLO : SM_BHI) + bRowOff;
        #pragma unroll 2
        for (int k0 = 0; k0 < 128; k0 += 16) {
            uint32_t a[4];
            ldm_x4(a, aBase + k0 * 2);
            #pragma unroll
            for (int j = 0; j < 8; j++) {
                uint32_t b[4];
                ldm_x4(b, bBase + (uint32_t)(j * 16 * STR + k0) * 2);
                mma_bf16(acc[2 * j],     a, b[0], b[1]);
                mma_bf16(acc[2 * j + 1], a, b[2], b[3]);
            }
        }
    }
    __syncthreads();

    {
        float* ep = (float*)(smem + SM_EP);
        const int r0 = wr + (lane >> 2);
        const int cq = 2 * (lane & 3);
        #pragma unroll
        for (int t = 0; t < 16; t++) {
            int col = t * 8 + cq;
            *(float2*)(ep + r0 * EPSTR + col)       = make_float2(acc[t][0], acc[t][1]);
            *(float2*)(ep + (r0 + 8) * EPSTR + col) = make_float2(acc[t][2], acc[t][3]);
        }
    }
    __syncthreads();
    {
        const float*  ep  = (const float*)(smem + SM_EP);
        const float4* g1v = (const float4*)(smem + SM_G1);
        const float4* g2v = (const float4*)(smem + SM_G2);
        const float4* g3v = (const float4*)(smem + SM_G3);
        #pragma unroll 4
        for (int i = tid; i < 64 * 32; i += 128) {
            int r = i >> 5, c4 = i & 31;
            int row = rowBase + r;
            if (row < N) {
                float s1 = __ldg(&c1[row]);
                float s2 = __ldg(&c2[row]);
                float s3 = __ldg(&du[row]);
                float4 v  = *(const float4*)(ep + r * EPSTR + c4 * 4);
                float4 a1 = g1v[c4], a2 = g2v[c4], a3 = g3v[c4];
                v.x += s1 * a1.x + s2 * a2.x + s3 * a3.x;
                v.y += s1 * a1.y + s2 * a2.y + s3 * a3.y;
                v.z += s1 * a1.z + s2 * a2.z + s3 * a3.z;
                v.w += s1 * a1.w + s2 * a2.w + s3 * a3.w;
                *(float4*)(Y + (size_t)row * D + c4 * 4) = v;
            }
        }
    }
}

// ---------------------------------------------------------------------------
// Small fp32 GEMM: C = A@B (128x128), plus vout = v@B. grid = 129 blocks.
// ---------------------------------------------------------------------------
__global__ __launch_bounds__(128)
void small_gemm_kernel(const float* __restrict__ A, const float* __restrict__ B,
                       const float* __restrict__ v, float* __restrict__ C,
                       float* __restrict__ vout)
{
    __shared__ float sA[128];
    int r = blockIdx.x;
    int j = threadIdx.x;
    const float* arow = (r < 128) ? (A + (size_t)r * D) : v;
    sA[j] = arow[j];
    __syncthreads();
    float s = 0.f;
    #pragma unroll 8
    for (int k = 0; k < 128; k++) s += sA[k] * B[k * D + j];
    if (r < 128) C[(size_t)r * D + j] = s;
    else vout[j] = s;
}

// Transpose + split W012 -> wthi/wtlo in [n=j][k] layout.
__global__ __launch_bounds__(256)
void wtsplit_kernel(const float* __restrict__ W,
                    __nv_bfloat16* __restrict__ hi, __nv_bfloat16* __restrict__ lo)
{
    int i = blockIdx.x * 256 + threadIdx.x;
    if (i >= D * D) return;
    int j = i >> 7, k = i & 127;
    __nv_bfloat16 h, l;
    bf16_split(W[k * D + j], h, l);
    hi[i] = h; lo[i] = l;
}

// ---------------------------------------------------------------------------
// CSR build (counting sort by destination).
// ---------------------------------------------------------------------------
__global__ __launch_bounds__(256)
void zero_int_kernel(int* __restrict__ p, int n)
{
    int i = blockIdx.x * blockDim.x + threadIdx.x;
    int stride = gridDim.x * blockDim.x;
    for (; i < n; i += stride) p[i] = 0;
}

__global__ __launch_bounds__(256)
void hist_kernel(const int* __restrict__ dest, int E, int* __restrict__ cnt)
{
    int i = blockIdx.x * blockDim.x + threadIdx.x;
    int stride = gridDim.x * blockDim.x;
    for (; i < E; i += stride) atomicAdd(&cnt[dest[i]], 1);
}

__global__ __launch_bounds__(1024)
void scanA_kernel(const int* __restrict__ cnt, int* __restrict__ rowptr,
                  int* __restrict__ bsum, int n)
{
    __shared__ int s[1024];
    int t = threadIdx.x;
    int i = blockIdx.x * 1024 + t;
    int x = (i < n) ? cnt[i] : 0;
    s[t] = x;
    __syncthreads();
    #pragma unroll
    for (int off = 1; off < 1024; off <<= 1) {
        int v = (t >= off) ? s[t - off] : 0;
        __syncthreads();
        s[t] += v;
        __syncthreads();
    }
    if (i < n) rowptr[i] = s[t] - x;
    if (t == 1023) bsum[blockIdx.x] = s[1023];
}

__global__ void scanB_kernel(int* __restrict__ bsum, int nb)
{
    __shared__ int s[64];
    int t = threadIdx.x;
    int v = (t < nb) ? bsum[t] : 0;
    s[t] = v;
    __syncthreads();
    #pragma unroll
    for (int off = 1; off < 64; off <<= 1) {
        int x = (t >= off) ? s[t - off] : 0;
        __syncthreads();
        s[t] += x;
        __syncthreads();
    }
    if (t < nb) bsum[t] = s[t] - v;
}

__global__ __launch_bounds__(1024)
void scanC_kernel(int* __restrict__ rowptr, int* __restrict__ off,
                  const int* __restrict__ bsum, int n, int E)
{
    int t = threadIdx.x;
    int i = blockIdx.x * 1024 + t;
    if (i < n) {
        int r = rowptr[i] + bsum[blockIdx.x];
        rowptr[i] = r;
        off[i] = r;
    }
    if (i == 0) rowptr[n] = E;
}

__global__ __launch_bounds__(256)
void fill_kernel(const int* __restrict__ dest, const int* __restrict__ src,
                 int E, int* __restrict__ off, int* __restrict__ srcs)
{
    int i = blockIdx.x * blockDim.x + threadIdx.x;
    int stride = gridDim.x * blockDim.x;
    for (; i < E; i += stride) {
        int d = dest[i];
        int p = atomicAdd(&off[d], 1);
        srcs[p] = src[i];
    }
}

// ---------------------------------------------------------------------------
// Degrees (float) from rowptr.
// ---------------------------------------------------------------------------
__global__ __launch_bounds__(256)
void degree_kernel(const int* __restrict__ rowptr, float* __restrict__ deg, int n)
{
    int i = blockIdx.x * 256 + threadIdx.x;
    if (i < n) deg[i] = (float)(rowptr[i + 1] - rowptr[i]);
}

// Scalar segment-sum: dst[d] = sum src[srcs[i]] over segment. One thread/node.
__global__ __launch_bounds__(256)
void scalar_agg_kernel(const float* __restrict__ src, float* __restrict__ dst,
                       const int* __restrict__ rowptr, const int* __restrict__ srcs,
                       int N)
{
    int d = blockIdx.x * 256 + threadIdx.x;
    if (d >= N) return;
    int b = __ldg(&rowptr[d]), e = __ldg(&rowptr[d + 1]);
    float s = 0.f;
    for (int i = b; i < e; i++) s += __ldg(&src[__ldg(&srcs[i])]);
    dst[d] = s;
}

// ---------------------------------------------------------------------------
// CSR feature aggregation. One warp per dest row; fp32 accumulation.
// ---------------------------------------------------------------------------
__device__ __forceinline__ float4 csr_gather_row(const float* __restrict__ src,
                                                 const int* __restrict__ srcs,
                                                 int beg, int end, int lane)
{
    float4 acc = make_float4(0.f, 0.f, 0.f, 0.f);
    int i = beg;
    for (; i + 4 <= end; i += 4) {
        int s0 = __ldg(&srcs[i + 0]);
        int s1 = __ldg(&srcs[i + 1]);
        int s2 = __ldg(&srcs[i + 2]);
        int s3 = __ldg(&srcs[i + 3]);
        float4 a = __ldg(reinterpret_cast<const float4*>(src + (size_t)s0 * D) + lane);
        float4 b = __ldg(reinterpret_cast<const float4*>(src + (size_t)s1 * D) + lane);
        float4 c = __ldg(reinterpret_cast<const float4*>(src + (size_t)s2 * D) + lane);
        float4 e = __ldg(reinterpret_cast<const float4*>(src + (size_t)s3 * D) + lane);
        acc.x += (a.x + b.x) + (c.x + e.x);
        acc.y += (a.y + b.y) + (c.y + e.y);
        acc.z += (a.z + b.z) + (c.z + e.z);
        acc.w += (a.w + b.w) + (c.w + e.w);
    }
    for (; i < end; i++) {
        int s0 = __ldg(&srcs[i]);
        float4 a = __ldg(reinterpret_cast<const float4*>(src + (size_t)s0 * D) + lane);
        acc.x += a.x; acc.y += a.y; acc.z += a.z; acc.w += a.w;
    }
    return acc;
}

__global__ __launch_bounds__(256)
void csr_aggregate_f32_kernel(const float* __restrict__ src,
                              float* __restrict__ dst,
                              const int* __restrict__ rowptr,
                              const int* __restrict__ srcs,
                              int N)
{
    int d = blockIdx.x * 8 + (threadIdx.x >> 5);
    if (d >= N) return;
    int lane = threadIdx.x & 31;
    float4 acc = csr_gather_row(src, srcs, __ldg(&rowptr[d]), __ldg(&rowptr[d + 1]), lane);
    reinterpret_cast<float4*>(dst + (size_t)d * D)[lane] = acc;
}

__global__ __launch_bounds__(256)
void csr_aggregate_split_kernel(const float* __restrict__ src,
                                __nv_bfloat16* __restrict__ dhi,
                                __nv_bfloat16* __restrict__ dlo,
                                const int* __restrict__ rowptr,
                                const int* __restrict__ srcs,
                                int N)
{
    int d = blockIdx.x * 8 + (threadIdx.x >> 5);
    if (d >= N) return;
    int lane = threadIdx.x & 31;
    float4 acc = csr_gather_row(src, srcs, __ldg(&rowptr[d]), __ldg(&rowptr[d + 1]), lane);

    __nv_bfloat16 h0, l0, h1, l1, h2, l2, h3, l3;
    bf16_split(acc.x, h0, l0); bf16_split(acc.y, h1, l1);
    bf16_split(acc.z, h2, l2); bf16_split(acc.w, h3, l3);
    __nv_bfloat162 hi01 = __nv_bfloat162(h0, h1), hi23 = __nv_bfloat162(h2, h3);
    __nv_bfloat162 lo01 = __nv_bfloat162(l0, l1), lo23 = __nv_bfloat162(l2, l3);
    uint2 hv, lv;
    hv.x = *(uint32_t*)&hi01; hv.y = *(uint32_t*)&hi23;
    lv.x = *(uint32_t*)&lo01; lv.y = *(uint32_t*)&lo23;
    *(uint2*)(dhi + (size_t)d * D + lane * 4) = hv;
    *(uint2*)(dlo + (size_t)d * D + lane * 4) = lv;
}

// ---------------------------------------------------------------------------
static void build_csr(const int* dest, const int* src, int E, int N,
                      int* rowptr, int* off, int* srcs, int* bsum)
{
    const int nb = (N + 1023) / 1024;
    zero_int_kernel<<<(N + 255) / 256, 256>>>(off, N);
    hist_kernel<<<256, 256>>>(dest, E, off);
    scanA_kernel<<<nb, 1024>>>(off, rowptr, bsum, N);
    scanB_kernel<<<1, 64>>>(bsum, nb);
    scanC_kernel<<<nb, 1024>>>(rowptr, off, bsum, N, E);
    fill_kernel<<<512, 256>>>(dest, src, E, off, srcs);
}

extern "C" void kernel_launch(void* const* d_in, const int* in_sizes, int n_in,
                              void* d_out, int out_size)
{
    const float* X_v    = (const float*)d_in[1];
    const int*   edge_u = (const int*)  d_in[2];
    const int*   edge_v = (const int*)  d_in[3];
    const float* W0     = (const float*)d_in[4];
    const float* b0     = (const float*)d_in[5];
    const float* W1     = (const float*)d_in[6];
    const float* b1     = (const float*)d_in[7];
    const float* W2     = (const float*)d_in[8];
    const float* b2     = (const float*)d_in[9];
    float*       out    = (float*)d_out;

    const int N_V = in_sizes[1] / D;
    const int E   = in_sizes[2];
    const int N_U = out_size / D;

    float *bufY, *bufZ, *P, *W012, *gg1, *gg2, *du, *dv, *ev, *c1, *c2;
    __nv_bfloat16 *hi, *lo, *wthi, *wtlo;
    cudaGetSymbolAddress((void**)&bufY, g_bufY);
    cudaGetSymbolAddress((void**)&bufZ, g_bufZ);
    cudaGetSymbolAddress((void**)&hi,   g_hi);
    cudaGetSymbolAddress((void**)&lo,   g_lo);
    cudaGetSymbolAddress((void**)&P,    g_P);
    cudaGetSymbolAddress((void**)&W012, g_W012);
    cudaGetSymbolAddress((void**)&wthi, g_wthi);
    cudaGetSymbolAddress((void**)&wtlo, g_wtlo);
    cudaGetSymbolAddress((void**)&gg1,  g_g1);
    cudaGetSymbolAddress((void**)&gg2,  g_g2);
    cudaGetSymbolAddress((void**)&du,   g_du);
    cudaGetSymbolAddress((void**)&dv,   g_dv);
    cudaGetSymbolAddress((void**)&ev,   g_ev);
    cudaGetSymbolAddress((void**)&c1,   g_c1);
    cudaGetSymbolAddress((void**)&c2,   g_c2);
    int *rowptr_u, *rowptr_v, *off_u, *off_v, *srcs_u, *srcs_v, *bsum_u, *bsum_v;
    cudaGetSymbolAddress((void**)&rowptr_u, g_rowptr_u);
    cudaGetSymbolAddress((void**)&rowptr_v, g_rowptr_v);
    cudaGetSymbolAddress((void**)&off_u, g_off_u);
    cudaGetSymbolAddress((void**)&off_v, g_off_v);
    cudaGetSymbolAddress((void**)&srcs_u, g_srcs_u);
    cudaGetSymbolAddress((void**)&srcs_v, g_srcs_v);
    cudaGetSymbolAddress((void**)&bsum_u, g_bsum_u);
    cudaGetSymbolAddress((void**)&bsum_v, g_bsum_v);

    cudaFuncSetAttribute(gemm_final_kernel,
                         cudaFuncAttributeMaxDynamicSharedMemorySize, SM_TOT);

    // CSR builds
    build_csr(edge_u, edge_v, E, N_U, rowptr_u, off_u, srcs_u, bsum_u); // v2u
    build_csr(edge_v, edge_u, E, N_V, rowptr_v, off_v, srcs_v, bsum_v); // u2v

    // Degrees and scalar chains:
    //   d_u, d_v; e_v = u2v(d_u); c1 = v2u(e_v); c2 = v2u(d_v)
    degree_kernel<<<(N_U + 255) / 256, 256>>>(rowptr_u, du, N_U);
    degree_kernel<<<(N_V + 255) / 256, 256>>>(rowptr_v, dv, N_V);
    scalar_agg_kernel<<<(N_V + 255) / 256, 256>>>(du, ev, rowptr_v, srcs_v, N_V);
    scalar_agg_kernel<<<(N_U + 255) / 256, 256>>>(ev, c1, rowptr_u, srcs_u, N_U);
    scalar_agg_kernel<<<(N_U + 255) / 256, 256>>>(dv, c2, rowptr_u, srcs_u, N_U);

    // Weight chain: P = W1@W2, g2 = b1@W2 ; W012 = W0@P, g1 = b0@P
    small_gemm_kernel<<<129, 128>>>(W1, W2, b1, P, gg2);
    small_gemm_kernel<<<129, 128>>>(W0, P, b0, W012, gg1);
    wtsplit_kernel<<<(D * D + 255) / 256, 256>>>(W012, wthi, wtlo);

    // Feature aggregations: S_u = v2u(X_v); T_v = u2v(S_u); R_u(split) = v2u(T_v)
    const int aggBlocksU = (N_U + 7) / 8;
    const int aggBlocksV = (N_V + 7) / 8;
    csr_aggregate_f32_kernel<<<aggBlocksU, 256>>>(X_v, bufY, rowptr_u, srcs_u, N_U);
    csr_aggregate_f32_kernel<<<aggBlocksV, 256>>>(bufY, bufZ, rowptr_v, srcs_v, N_V);
    csr_aggregate_split_kernel<<<aggBlocksU, 256>>>(bufZ, hi, lo, rowptr_u, srcs_u, N_U);

    // Final GEMM with fused rank-1 bias terms.
    const int gemmBlocksU = (N_U + 63) / 64;
    gemm_final_kernel<<<gemmBlocksU, 128, SM_TOT>>>(hi, lo, wthi, wtlo,
                                                    gg1, gg2, b2, c1, c2, du,
                                                    out, N_U);
}

// round 7
// speedup vs baseline: 2.5051x; 1.3370x over previous
#include <cuda_runtime.h>
#include <cuda_bf16.h>
#include <cstdint>

#define D 128
#define MAXN 50176
#define MAXE 640000

typedef unsigned long long u64;

// ---------------------------------------------------------------------------
// Scratch (no cudaMalloc allowed).
// ---------------------------------------------------------------------------
__device__ float         g_bufY[(size_t)MAXN * D];   // S_u = v2u(X_v)
__device__ float         g_bufZ[(size_t)MAXN * D];   // T_v = u2v(S_u)
__device__ __nv_bfloat16 g_hi[(size_t)MAXN * D];     // R split hi
__device__ __nv_bfloat16 g_lo[(size_t)MAXN * D];     // R split lo
__device__ float         g_P[D * D];                 // W1@W2
__device__ __nv_bfloat16 g_wthi[D * D];              // (W0@W1@W2)^T split
__device__ __nv_bfloat16 g_wtlo[D * D];
__device__ float         g_g1[D];                    // b0@W1@W2
__device__ float         g_g2[D];                    // b1@W2
__device__ float         g_du[MAXN];
__device__ float         g_dv[MAXN];
__device__ float         g_ev[MAXN];                 // u2v(d_u)
__device__ float         g_c1[MAXN];                 // v2u(e_v)
__device__ float         g_c2[MAXN];                 // v2u(d_v)

// CSR structures.
__device__ int g_rowptr_u[MAXN + 1];
__device__ int g_rowptr_v[MAXN + 1];
__device__ int g_off_u[MAXN];
__device__ int g_off_v[MAXN];
__device__ int g_srcs_u[MAXE];
__device__ int g_srcs_v[MAXE];
__device__ int g_bsum_u[64];
__device__ int g_bsum_v[64];

// ---------------------------------------------------------------------------
// mma.sync / ldmatrix helpers (baseline PTX, works on compute_103)
// ---------------------------------------------------------------------------
__device__ __forceinline__ uint32_t smem_u32(const void* p) {
    uint32_t a;
    asm("{ .reg .u64 t; cvta.to.shared.u64 t, %1; cvt.u32.u64 %0, t; }" : "=r"(a) : "l"(p));
    return a;
}

__device__ __forceinline__ void ldm_x4(uint32_t (&r)[4], uint32_t addr) {
    asm volatile("ldmatrix.sync.aligned.m8n8.x4.shared.b16 {%0,%1,%2,%3}, [%4];"
                 : "=r"(r[0]), "=r"(r[1]), "=r"(r[2]), "=r"(r[3]) : "r"(addr));
}

__device__ __forceinline__ void mma_bf16(float (&c)[4], const uint32_t (&a)[4],
                                         uint32_t b0, uint32_t b1) {
    asm volatile(
        "mma.sync.aligned.m16n8k16.row.col.f32.bf16.bf16.f32 "
        "{%0,%1,%2,%3}, {%4,%5,%6,%7}, {%8,%9}, {%0,%1,%2,%3};"
        : "+f"(c[0]), "+f"(c[1]), "+f"(c[2]), "+f"(c[3])
        : "r"(a[0]), "r"(a[1]), "r"(a[2]), "r"(a[3]), "r"(b0), "r"(b1));
}

__device__ __forceinline__ void bf16_split(float f, __nv_bfloat16& h, __nv_bfloat16& l) {
    h = __float2bfloat16(f);
    l = __float2bfloat16(f - __bfloat162float(h));
}

// ---------------------------------------------------------------------------
// Final tensor GEMM: out[64-row tile] = R @ W012 + c1*g1 + c2*g2 + du*g3
// ---------------------------------------------------------------------------
#define STR 136
#define SM_G1   0
#define SM_G2   512
#define SM_G3   1024
#define SM_AHI  1536
#define SM_ALO  (SM_AHI + 64 * 272)
#define SM_BHI  (SM_ALO + 64 * 272)
#define SM_BLO  (SM_BHI + 128 * 272)
#define SM_TOT  (SM_BLO + 128 * 272)     // 105984
#define SM_EP   1536
#define EPSTR   132

__global__ __launch_bounds__(128, 2)
void gemm_final_kernel(const __nv_bfloat16* __restrict__ Ahi,
                       const __nv_bfloat16* __restrict__ Alo,
                       const __nv_bfloat16* __restrict__ Bhi,
                       const __nv_bfloat16* __restrict__ Blo,
                       const float* __restrict__ g1,
                       const float* __restrict__ g2,
                       const float* __restrict__ g3,
                       const float* __restrict__ c1,
                       const float* __restrict__ c2,
                       const float* __restrict__ du,
                       float* __restrict__ Y,
                       int N)
{
    extern __shared__ char smem[];
    const uint32_t sb = smem_u32(smem);
    const int tid  = threadIdx.x;
    const int lane = tid & 31;
    const int warp = tid >> 5;
    const int rowBase = blockIdx.x * 64;

    ((float*)(smem + SM_G1))[tid] = g1[tid];
    ((float*)(smem + SM_G2))[tid] = g2[tid];
    ((float*)(smem + SM_G3))[tid] = g3[tid];

    #pragma unroll 4
    for (int i = tid; i < 128 * 16; i += 128) {
        int n = i >> 4, c = i & 15;
        uint32_t so = (uint32_t)(n * 272 + c * 16);
        *(uint4*)(smem + SM_BHI + so) = *(const uint4*)(Bhi + (size_t)n * D + c * 8);
        *(uint4*)(smem + SM_BLO + so) = *(const uint4*)(Blo + (size_t)n * D + c * 8);
    }
    #pragma unroll 4
    for (int i = tid; i < 64 * 16; i += 128) {
        int r = i >> 4, c = i & 15;
        int row = rowBase + r;
        uint4 vh = make_uint4(0, 0, 0, 0), vl = vh;
        if (row < N) {
            vh = *(const uint4*)(Ahi + (size_t)row * D + c * 8);
            vl = *(const uint4*)(Alo + (size_t)row * D + c * 8);
        }
        uint32_t so = (uint32_t)(r * 272 + c * 16);
        *(uint4*)(smem + SM_AHI + so) = vh;
        *(uint4*)(smem + SM_ALO + so) = vl;
    }
    __syncthreads();

    float acc[16][4];
    #pragma unroll
    for (int t = 0; t < 16; t++) {
        acc[t][0] = 0.f; acc[t][1] = 0.f; acc[t][2] = 0.f; acc[t][3] = 0.f;
    }

    const int wr = warp * 16;
    const uint32_t aRowOff = (uint32_t)((wr + (lane & 15)) * STR + ((lane >> 4) << 3)) * 2;
    const int nOff  = (lane & 7) + ((lane >> 4) & 1) * 8;
    const int kHalf = ((lane >> 3) & 1) * 8;
    const uint32_t bRowOff = (uint32_t)(nOff * STR + kHalf) * 2;

    #pragma unroll 1
    for (int pass = 0; pass < 3; pass++) {
        uint32_t aBase = sb + ((pass == 2) ? SM_ALO : SM_AHI) + aRowOff;
        uint32_t bBase = sb + ((pass == 1) ? SM_BLO : SM_BHI) + bRowOff;
        #pragma unroll 2
        for (int k0 = 0; k0 < 128; k0 += 16) {
            uint32_t a[4];
            ldm_x4(a, aBase + k0 * 2);
            #pragma unroll
            for (int j = 0; j < 8; j++) {
                uint32_t b[4];
                ldm_x4(b, bBase + (uint32_t)(j * 16 * STR + k0) * 2);
                mma_bf16(acc[2 * j],     a, b[0], b[1]);
                mma_bf16(acc[2 * j + 1], a, b[2], b[3]);
            }
        }
    }
    __syncthreads();

    {
        float* ep = (float*)(smem + SM_EP);
        const int r0 = wr + (lane >> 2);
        const int cq = 2 * (lane & 3);
        #pragma unroll
        for (int t = 0; t < 16; t++) {
            int col = t * 8 + cq;
            *(float2*)(ep + r0 * EPSTR + col)       = make_float2(acc[t][0], acc[t][1]);
            *(float2*)(ep + (r0 + 8) * EPSTR + col) = make_float2(acc[t][2], acc[t][3]);
        }
    }
    __syncthreads();
    {
        const float*  ep  = (const float*)(smem + SM_EP);
        const float4* g1v = (const float4*)(smem + SM_G1);
        const float4* g2v = (const float4*)(smem + SM_G2);
        const float4* g3v = (const float4*)(smem + SM_G3);
        #pragma unroll 4
        for (int i = tid; i < 64 * 32; i += 128) {
            int r = i >> 5, c4 = i & 31;
            int row = rowBase + r;
            if (row < N) {
                float s1 = __ldg(&c1[row]);
                float s2 = __ldg(&c2[row]);
                float s3 = __ldg(&du[row]);
                float4 v  = *(const float4*)(ep + r * EPSTR + c4 * 4);
                float4 a1 = g1v[c4], a2 = g2v[c4], a3 = g3v[c4];
                v.x += s1 * a1.x + s2 * a2.x + s3 * a3.x;
                v.y += s1 * a1.y + s2 * a2.y + s3 * a3.y;
                v.z += s1 * a1.z + s2 * a2.z + s3 * a3.z;
                v.w += s1 * a1.w + s2 * a2.w + s3 * a3.w;
                *(float4*)(Y + (size_t)row * D + c4 * 4) = v;
            }
        }
    }
}

// ---------------------------------------------------------------------------
// Small fp32 GEMMs for the weight chain.
// ---------------------------------------------------------------------------
__global__ __launch_bounds__(128)
void small_gemm_kernel(const float* __restrict__ A, const float* __restrict__ B,
                       const float* __restrict__ v, float* __restrict__ C,
                       float* __restrict__ vout)
{
    __shared__ float sA[128];
    int r = blockIdx.x;
    int j = threadIdx.x;
    const float* arow = (r < 128) ? (A + (size_t)r * D) : v;
    sA[j] = arow[j];
    __syncthreads();
    float s = 0.f;
    #pragma unroll 8
    for (int k = 0; k < 128; k++) s += sA[k] * B[k * D + j];
    if (r < 128) C[(size_t)r * D + j] = s;
    else vout[j] = s;
}

// W012 = W0@P with transpose+split epilogue (writes B operand directly), g1 = b0@P.
__global__ __launch_bounds__(128)
void small_gemm_split_kernel(const float* __restrict__ A, const float* __restrict__ B,
                             const float* __restrict__ v,
                             __nv_bfloat16* __restrict__ wthi,
                             __nv_bfloat16* __restrict__ wtlo,
                             float* __restrict__ vout)
{
    __shared__ float sA[128];
    int r = blockIdx.x;
    int j = threadIdx.x;
    const float* arow = (r < 128) ? (A + (size_t)r * D) : v;
    sA[j] = arow[j];
    __syncthreads();
    float s = 0.f;
    #pragma unroll 8
    for (int k = 0; k < 128; k++) s += sA[k] * B[k * D + j];
    if (r < 128) {
        __nv_bfloat16 h, l;
        bf16_split(s, h, l);
        wthi[(size_t)j * D + r] = h;   // [n=j][k=r] layout for the B operand
        wtlo[(size_t)j * D + r] = l;
    } else {
        vout[j] = s;
    }
}

// ---------------------------------------------------------------------------
// CSR build (counting sort by destination).
// ---------------------------------------------------------------------------
__global__ __launch_bounds__(256)
void zero_int_kernel(int* __restrict__ p, int n)
{
    int i = blockIdx.x * blockDim.x + threadIdx.x;
    int stride = gridDim.x * blockDim.x;
    for (; i < n; i += stride) p[i] = 0;
}

__global__ __launch_bounds__(256)
void hist_kernel(const int* __restrict__ dest, int E, int* __restrict__ cnt)
{
    int i = blockIdx.x * blockDim.x + threadIdx.x;
    int stride = gridDim.x * blockDim.x;
    for (; i < E; i += stride) atomicAdd(&cnt[dest[i]], 1);
}

// scanA also emits float degrees (deg[i] = cnt[i]).
__global__ __launch_bounds__(1024)
void scanA_kernel(const int* __restrict__ cnt, int* __restrict__ rowptr,
                  int* __restrict__ bsum, float* __restrict__ deg, int n)
{
    __shared__ int s[1024];
    int t = threadIdx.x;
    int i = blockIdx.x * 1024 + t;
    int x = (i < n) ? cnt[i] : 0;
    if (i < n) deg[i] = (float)x;
    s[t] = x;
    __syncthreads();
    #pragma unroll
    for (int off = 1; off < 1024; off <<= 1) {
        int v = (t >= off) ? s[t - off] : 0;
        __syncthreads();
        s[t] += v;
        __syncthreads();
    }
    if (i < n) rowptr[i] = s[t] - x;
    if (t == 1023) bsum[blockIdx.x] = s[1023];
}

__global__ void scanB_kernel(int* __restrict__ bsum, int nb)
{
    __shared__ int s[64];
    int t = threadIdx.x;
    int v = (t < nb) ? bsum[t] : 0;
    s[t] = v;
    __syncthreads();
    #pragma unroll
    for (int off = 1; off < 64; off <<= 1) {
        int x = (t >= off) ? s[t - off] : 0;
        __syncthreads();
        s[t] += x;
        __syncthreads();
    }
    if (t < nb) bsum[t] = s[t] - v;
}

__global__ __launch_bounds__(1024)
void scanC_kernel(int* __restrict__ rowptr, int* __restrict__ off,
                  const int* __restrict__ bsum, int n, int E)
{
    int t = threadIdx.x;
    int i = blockIdx.x * 1024 + t;
    if (i < n) {
        int r = rowptr[i] + bsum[blockIdx.x];
        rowptr[i] = r;
        off[i] = r;
    }
    if (i == 0) rowptr[n] = E;
}

__global__ __launch_bounds__(256)
void fill_kernel(const int* __restrict__ dest, const int* __restrict__ src,
                 int E, int* __restrict__ off, int* __restrict__ srcs)
{
    int i = blockIdx.x * blockDim.x + threadIdx.x;
    int stride = gridDim.x * blockDim.x;
    for (; i < E; i += stride) {
        int d = dest[i];
        int p = atomicAdd(&off[d], 1);
        srcs[p] = src[i];
    }
}

// ---------------------------------------------------------------------------
// Scalar segment-sums.
// ---------------------------------------------------------------------------
__global__ __launch_bounds__(256)
void scalar_agg_kernel(const float* __restrict__ src, float* __restrict__ dst,
                       const int* __restrict__ rowptr, const int* __restrict__ srcs,
                       int N)
{
    int d = blockIdx.x * 256 + threadIdx.x;
    if (d >= N) return;
    int b = __ldg(&rowptr[d]), e = __ldg(&rowptr[d + 1]);
    float s = 0.f;
    for (int i = b; i < e; i++) s += __ldg(&src[__ldg(&srcs[i])]);
    dst[d] = s;
}

// Fused: c1 = v2u(ev), c2 = v2u(dv) — one pass over indices.
__global__ __launch_bounds__(256)
void c1c2_kernel(const float* __restrict__ ev, const float* __restrict__ dv,
                 float* __restrict__ c1, float* __restrict__ c2,
                 const int* __restrict__ rowptr, const int* __restrict__ srcs,
                 int N)
{
    int d = blockIdx.x * 256 + threadIdx.x;
    if (d >= N) return;
    int b = __ldg(&rowptr[d]), e = __ldg(&rowptr[d + 1]);
    float s1 = 0.f, s2 = 0.f;
    for (int i = b; i < e; i++) {
        int s = __ldg(&srcs[i]);
        s1 += __ldg(&ev[s]);
        s2 += __ldg(&dv[s]);
    }
    c1[d] = s1;
    c2[d] = s2;
}

// ---------------------------------------------------------------------------
// CSR feature aggregation. One warp per dest row; fp32 accumulation.
// ---------------------------------------------------------------------------
__device__ __forceinline__ float4 csr_gather_row(const float* __restrict__ src,
                                                 const int* __restrict__ srcs,
                                                 int beg, int end, int lane)
{
    float4 acc = make_float4(0.f, 0.f, 0.f, 0.f);
    int i = beg;
    for (; i + 4 <= end; i += 4) {
        int s0 = __ldg(&srcs[i + 0]);
        int s1 = __ldg(&srcs[i + 1]);
        int s2 = __ldg(&srcs[i + 2]);
        int s3 = __ldg(&srcs[i + 3]);
        float4 a = __ldg(reinterpret_cast<const float4*>(src + (size_t)s0 * D) + lane);
        float4 b = __ldg(reinterpret_cast<const float4*>(src + (size_t)s1 * D) + lane);
        float4 c = __ldg(reinterpret_cast<const float4*>(src + (size_t)s2 * D) + lane);
        float4 e = __ldg(reinterpret_cast<const float4*>(src + (size_t)s3 * D) + lane);
        acc.x += (a.x + b.x) + (c.x + e.x);
        acc.y += (a.y + b.y) + (c.y + e.y);
        acc.z += (a.z + b.z) + (c.z + e.z);
        acc.w += (a.w + b.w) + (c.w + e.w);
    }
    for (; i < end; i++) {
        int s0 = __ldg(&srcs[i]);
        float4 a = __ldg(reinterpret_cast<const float4*>(src + (size_t)s0 * D) + lane);
        acc.x += a.x; acc.y += a.y; acc.z += a.z; acc.w += a.w;
    }
    return acc;
}

__global__ __launch_bounds__(256)
void csr_aggregate_f32_kernel(const float* __restrict__ src,
                              float* __restrict__ dst,
                              const int* __restrict__ rowptr,
                              const int* __restrict__ srcs,
                              int N)
{
    int d = blockIdx.x * 8 + (threadIdx.x >> 5);
    if (d >= N) return;
    int lane = threadIdx.x & 31;
    float4 acc = csr_gather_row(src, srcs, __ldg(&rowptr[d]), __ldg(&rowptr[d + 1]), lane);
    reinterpret_cast<float4*>(dst + (size_t)d * D)[lane] = acc;
}

__global__ __launch_bounds__(256)
void csr_aggregate_split_kernel(const float* __restrict__ src,
                                __nv_bfloat16* __restrict__ dhi,
                                __nv_bfloat16* __restrict__ dlo,
                                const int* __restrict__ rowptr,
                                const int* __restrict__ srcs,
                                int N)
{
    int d = blockIdx.x * 8 + (threadIdx.x >> 5);
    if (d >= N) return;
    int lane = threadIdx.x & 31;
    float4 acc = csr_gather_row(src, srcs, __ldg(&rowptr[d]), __ldg(&rowptr[d + 1]), lane);

    __nv_bfloat16 h0, l0, h1, l1, h2, l2, h3, l3;
    bf16_split(acc.x, h0, l0); bf16_split(acc.y, h1, l1);
    bf16_split(acc.z, h2, l2); bf16_split(acc.w, h3, l3);
    __nv_bfloat162 hi01 = __nv_bfloat162(h0, h1), hi23 = __nv_bfloat162(h2, h3);
    __nv_bfloat162 lo01 = __nv_bfloat162(l0, l1), lo23 = __nv_bfloat162(l2, l3);
    uint2 hv, lv;
    hv.x = *(uint32_t*)&hi01; hv.y = *(uint32_t*)&hi23;
    lv.x = *(uint32_t*)&lo01; lv.y = *(uint32_t*)&lo23;
    *(uint2*)(dhi + (size_t)d * D + lane * 4) = hv;
    *(uint2*)(dlo + (size_t)d * D + lane * 4) = lv;
}

// ---------------------------------------------------------------------------
extern "C" void kernel_launch(void* const* d_in, const int* in_sizes, int n_in,
                              void* d_out, int out_size)
{
    const float* X_v    = (const float*)d_in[1];
    const int*   edge_u = (const int*)  d_in[2];
    const int*   edge_v = (const int*)  d_in[3];
    const float* W0     = (const float*)d_in[4];
    const float* b0     = (const float*)d_in[5];
    const float* W1     = (const float*)d_in[6];
    const float* b1     = (const float*)d_in[7];
    const float* W2     = (const float*)d_in[8];
    const float* b2     = (const float*)d_in[9];
    float*       out    = (float*)d_out;

    const int N_V = in_sizes[1] / D;
    const int E   = in_sizes[2];
    const int N_U = out_size / D;

    float *bufY, *bufZ, *P, *gg1, *gg2, *du, *dv, *ev, *c1, *c2;
    __nv_bfloat16 *hi, *lo, *wthi, *wtlo;
    cudaGetSymbolAddress((void**)&bufY, g_bufY);
    cudaGetSymbolAddress((void**)&bufZ, g_bufZ);
    cudaGetSymbolAddress((void**)&hi,   g_hi);
    cudaGetSymbolAddress((void**)&lo,   g_lo);
    cudaGetSymbolAddress((void**)&P,    g_P);
    cudaGetSymbolAddress((void**)&wthi, g_wthi);
    cudaGetSymbolAddress((void**)&wtlo, g_wtlo);
    cudaGetSymbolAddress((void**)&gg1,  g_g1);
    cudaGetSymbolAddress((void**)&gg2,  g_g2);
    cudaGetSymbolAddress((void**)&du,   g_du);
    cudaGetSymbolAddress((void**)&dv,   g_dv);
    cudaGetSymbolAddress((void**)&ev,   g_ev);
    cudaGetSymbolAddress((void**)&c1,   g_c1);
    cudaGetSymbolAddress((void**)&c2,   g_c2);
    int *rowptr_u, *rowptr_v, *off_u, *off_v, *srcs_u, *srcs_v, *bsum_u, *bsum_v;
    cudaGetSymbolAddress((void**)&rowptr_u, g_rowptr_u);
    cudaGetSymbolAddress((void**)&rowptr_v, g_rowptr_v);
    cudaGetSymbolAddress((void**)&off_u, g_off_u);
    cudaGetSymbolAddress((void**)&off_v, g_off_v);
    cudaGetSymbolAddress((void**)&srcs_u, g_srcs_u);
    cudaGetSymbolAddress((void**)&srcs_v, g_srcs_v);
    cudaGetSymbolAddress((void**)&bsum_u, g_bsum_u);
    cudaGetSymbolAddress((void**)&bsum_v, g_bsum_v);

    cudaFuncSetAttribute(gemm_final_kernel,
                         cudaFuncAttributeMaxDynamicSharedMemorySize, SM_TOT);

    // One-time infra: two non-blocking side streams + fork/join events.
    static cudaStream_t sV = nullptr, sW = nullptr;
    static cudaEvent_t eFork = nullptr, eU = nullptr, eBV = nullptr,
                       eSC = nullptr, eW = nullptr;
    if (sV == nullptr) {
        cudaStreamCreateWithFlags(&sV, cudaStreamNonBlocking);
        cudaStreamCreateWithFlags(&sW, cudaStreamNonBlocking);
        cudaEventCreateWithFlags(&eFork, cudaEventDisableTiming);
        cudaEventCreateWithFlags(&eU,    cudaEventDisableTiming);
        cudaEventCreateWithFlags(&eBV,   cudaEventDisableTiming);
        cudaEventCreateWithFlags(&eSC,   cudaEventDisableTiming);
        cudaEventCreateWithFlags(&eW,    cudaEventDisableTiming);
    }

    const int nb_u = (N_U + 1023) / 1024;
    const int nb_v = (N_V + 1023) / 1024;
    const int aggBlocksU = (N_U + 7) / 8;
    const int aggBlocksV = (N_V + 7) / 8;
    const int gemmBlocksU = (N_U + 63) / 64;

    // ---- fork ----
    cudaEventRecord(eFork, 0);
    cudaStreamWaitEvent(sV, eFork, 0);
    cudaStreamWaitEvent(sW, eFork, 0);

    // ---- main stream: build_u (v2u CSR) ----
    zero_int_kernel<<<(N_U + 255) / 256, 256, 0, 0>>>(off_u, N_U);
    hist_kernel<<<256, 256, 0, 0>>>(edge_u, E, off_u);
    scanA_kernel<<<nb_u, 1024, 0, 0>>>(off_u, rowptr_u, bsum_u, du, N_U);
    scanB_kernel<<<1, 64, 0, 0>>>(bsum_u, nb_u);
    scanC_kernel<<<nb_u, 1024, 0, 0>>>(rowptr_u, off_u, bsum_u, N_U, E);
    fill_kernel<<<512, 256, 0, 0>>>(edge_u, edge_v, E, off_u, srcs_u);
    cudaEventRecord(eU, 0);

    // ---- stream V: build_v (u2v CSR) + scalar-degree chain ----
    zero_int_kernel<<<(N_V + 255) / 256, 256, 0, sV>>>(off_v, N_V);
    hist_kernel<<<256, 256, 0, sV>>>(edge_v, E, off_v);
    scanA_kernel<<<nb_v, 1024, 0, sV>>>(off_v, rowptr_v, bsum_v, dv, N_V);
    scanB_kernel<<<1, 64, 0, sV>>>(bsum_v, nb_v);
    scanC_kernel<<<nb_v, 1024, 0, sV>>>(rowptr_v, off_v, bsum_v, N_V, E);
    fill_kernel<<<512, 256, 0, sV>>>(edge_v, edge_u, E, off_v, srcs_v);
    cudaEventRecord(eBV, sV);
    cudaStreamWaitEvent(sV, eU, 0);   // needs du + srcs_u/rowptr_u
    scalar_agg_kernel<<<(N_V + 255) / 256, 256, 0, sV>>>(du, ev, rowptr_v, srcs_v, N_V);
    c1c2_kernel<<<(N_U + 255) / 256, 256, 0, sV>>>(ev, dv, c1, c2, rowptr_u, srcs_u, N_U);
    cudaEventRecord(eSC, sV);

    // ---- stream W: weight chain ----
    small_gemm_kernel<<<129, 128, 0, sW>>>(W1, W2, b1, P, gg2);
    small_gemm_split_kernel<<<129, 128, 0, sW>>>(W0, P, b0, wthi, wtlo, gg1);
    cudaEventRecord(eW, sW);

    // ---- main stream: feature aggregation chain ----
    csr_aggregate_f32_kernel<<<aggBlocksU, 256, 0, 0>>>(X_v, bufY, rowptr_u, srcs_u, N_U);
    cudaStreamWaitEvent(0, eBV, 0);
    csr_aggregate_f32_kernel<<<aggBlocksV, 256, 0, 0>>>(bufY, bufZ, rowptr_v, srcs_v, N_V);
    csr_aggregate_split_kernel<<<aggBlocksU, 256, 0, 0>>>(bufZ, hi, lo, rowptr_u, srcs_u, N_U);

    // ---- join + final GEMM ----
    cudaStreamWaitEvent(0, eSC, 0);
    cudaStreamWaitEvent(0, eW, 0);
    gemm_final_kernel<<<gemmBlocksU, 128, SM_TOT, 0>>>(hi, lo, wthi, wtlo,
                                                       gg1, gg2, b2, c1, c2, du,
                                                       out, N_U);
}